// round 12
// baseline (speedup 1.0000x reference)
#include <cuda_runtime.h>
#include <cuda_bf16.h>
#include <math.h>
#include <stdint.h>

#define T_STEPS 64
#define B_SZ    64
#define H_SZ    256
#define G_SZ    1024
#define M_TOT   4096      // T*B
#define V_SZ    32000

// ---------------- scratch ----------------------------------------------------
__device__ __align__(256) float g_bufA[M_TOT * H_SZ];
__device__ __align__(256) float g_bufB[M_TOT * H_SZ];
__device__ __align__(256) float g_gx[M_TOT * G_SZ];
__device__ __align__(256) float g_hfin[3 * B_SZ * H_SZ];
__device__ __align__(256) float g_cfin[3 * B_SZ * H_SZ];

// ================= bf16 2-split helpers ======================================
__device__ __forceinline__ uint32_t pack_bf2(unsigned short lo, unsigned short hi) {
    return ((uint32_t)hi << 16) | (uint32_t)lo;
}
__device__ __forceinline__ void split_bf(float a, unsigned short& h, unsigned short& l) {
    __nv_bfloat16 hb = __float2bfloat16_rn(a);
    float hf = __bfloat162float(hb);
    __nv_bfloat16 lb = __float2bfloat16_rn(a - hf);
    h = __bfloat16_as_ushort(hb);
    l = __bfloat16_as_ushort(lb);
}
__device__ __forceinline__ void split_store4(unsigned short* dhi, unsigned short* dlo, float4 a) {
    unsigned short h0, h1, h2, h3, l0, l1, l2, l3;
    split_bf(a.x, h0, l0); split_bf(a.y, h1, l1);
    split_bf(a.z, h2, l2); split_bf(a.w, h3, l3);
    uint2 hv; hv.x = pack_bf2(h0, h1); hv.y = pack_bf2(h2, h3);
    uint2 lv; lv.x = pack_bf2(l0, l1); lv.y = pack_bf2(l2, l3);
    *(uint2*)dhi = hv;
    *(uint2*)dlo = lv;
}

#define MMA_BF16(c, a, b) \
    asm volatile("mma.sync.aligned.m16n8k16.row.col.f32.bf16.bf16.f32 " \
        "{%0,%1,%2,%3}, {%4,%5,%6,%7}, {%8,%9}, {%0,%1,%2,%3};" \
        : "+f"((c)[0]), "+f"((c)[1]), "+f"((c)[2]), "+f"((c)[3]) \
        : "r"((a)[0]), "r"((a)[1]), "r"((a)[2]), "r"((a)[3]), \
          "r"((b)[0]), "r"((b)[1]))

__device__ __forceinline__ uint32_t smem_u32(const void* p) {
    uint32_t a;
    asm("{ .reg .u64 t; cvta.to.shared.u64 t, %1; cvt.u32.u64 %0, t; }" : "=r"(a) : "l"(p));
    return a;
}

// ================= bf16 2-split mma.sync GEMM ================================
// K-loop unroll 1: keeps one chunk of fragments live (no register spills).
#define BG_LD   264
#define BG_AHI  0
#define BG_ALO  (128 * BG_LD)
#define BG_BHI  (2 * 128 * BG_LD)
#define BG_BLO  (2 * 128 * BG_LD + 64 * BG_LD)
#define BG_SMEM ((2 * 128 * BG_LD + 2 * 64 * BG_LD) * 2)

__global__ void __launch_bounds__(256, 1) bgemm(
    const float* __restrict__ A, const float* __restrict__ W,
    const float* __restrict__ b1, const float* __restrict__ b2,
    float* __restrict__ C, int Ntot)
{
    extern __shared__ __align__(16) unsigned short bsm[];

    int tid = threadIdx.x;
    int wid = tid >> 5, lane = tid & 31;
    int g = lane >> 2, t = lane & 3;
    int warpM = wid >> 1, warpN = wid & 1;

    int nN = Ntot >> 6;
    int NT = nN << 5;
    int per = (NT + gridDim.x - 1) / gridDim.x;
    int tau0 = blockIdx.x * per;
    int tau1 = tau0 + per; if (tau1 > NT) tau1 = NT;
    int mPrev = -1;

    for (int tau = tau0; tau < tau1; tau++) {
        int mT = tau / nN, nT = tau - mT * nN;
        int m0 = mT << 7, n0 = nT << 6;

        __syncthreads();
        if (mT != mPrev) {
            const float* Ap = A + (size_t)m0 * 256;
#pragma unroll
            for (int v = 0; v < 32; v++) {
                int id = tid + 256 * v;
                int r = id >> 6, c4 = (id & 63) * 4;
                float4 a = __ldg((const float4*)(Ap + (size_t)r * 256 + c4));
                int hidx = r * BG_LD + c4;
                split_store4(bsm + BG_AHI + hidx, bsm + BG_ALO + hidx, a);
            }
            mPrev = mT;
        }
        {
            const float* Wp = W + (size_t)n0 * 256;
#pragma unroll
            for (int v = 0; v < 16; v++) {
                int id = tid + 256 * v;
                int r = id >> 6, c4 = (id & 63) * 4;
                float4 a = __ldg((const float4*)(Wp + (size_t)r * 256 + c4));
                int hidx = r * BG_LD + c4;
                split_store4(bsm + BG_BHI + hidx, bsm + BG_BLO + hidx, a);
            }
        }
        __syncthreads();

        float acc[2][4][4];
#pragma unroll
        for (int i = 0; i < 2; i++)
#pragma unroll
            for (int j = 0; j < 4; j++)
#pragma unroll
                for (int k = 0; k < 4; k++) acc[i][j][k] = 0.f;

        int aRow = warpM * 32;
        int bRow = warpN * 32;

#pragma unroll 1
        for (int kk = 0; kk < 256; kk += 16) {
            uint32_t ah[2][4], al[2][4];
#pragma unroll
            for (int ms = 0; ms < 2; ms++) {
                int r0 = aRow + ms * 16 + g;
                int i00 = r0 * BG_LD + 2 * t + kk;
                int i10 = (r0 + 8) * BG_LD + 2 * t + kk;
                ah[ms][0] = *(const uint32_t*)(bsm + BG_AHI + i00);
                ah[ms][1] = *(const uint32_t*)(bsm + BG_AHI + i10);
                ah[ms][2] = *(const uint32_t*)(bsm + BG_AHI + i00 + 8);
                ah[ms][3] = *(const uint32_t*)(bsm + BG_AHI + i10 + 8);
                al[ms][0] = *(const uint32_t*)(bsm + BG_ALO + i00);
                al[ms][1] = *(const uint32_t*)(bsm + BG_ALO + i10);
                al[ms][2] = *(const uint32_t*)(bsm + BG_ALO + i00 + 8);
                al[ms][3] = *(const uint32_t*)(bsm + BG_ALO + i10 + 8);
            }
            uint32_t bh[4][2], bl[4][2];
#pragma unroll
            for (int ns = 0; ns < 4; ns++) {
                int rw = bRow + ns * 8 + g;
                int ib = rw * BG_LD + 2 * t + kk;
                bh[ns][0] = *(const uint32_t*)(bsm + BG_BHI + ib);
                bh[ns][1] = *(const uint32_t*)(bsm + BG_BHI + ib + 8);
                bl[ns][0] = *(const uint32_t*)(bsm + BG_BLO + ib);
                bl[ns][1] = *(const uint32_t*)(bsm + BG_BLO + ib + 8);
            }
#pragma unroll
            for (int ms = 0; ms < 2; ms++)
#pragma unroll
                for (int ns = 0; ns < 4; ns++) {
                    MMA_BF16(acc[ms][ns], ah[ms], bh[ns]);
                    MMA_BF16(acc[ms][ns], ah[ms], bl[ns]);
                    MMA_BF16(acc[ms][ns], al[ms], bh[ns]);
                }
        }

#pragma unroll
        for (int ms = 0; ms < 2; ms++) {
            int row0 = m0 + aRow + ms * 16 + g;
#pragma unroll
            for (int ns = 0; ns < 4; ns++) {
                int col = n0 + bRow + ns * 8 + 2 * t;
                float bv0 = __ldg(b1 + col), bv1 = __ldg(b1 + col + 1);
                if (b2) { bv0 += __ldg(b2 + col); bv1 += __ldg(b2 + col + 1); }
                float2 o0, o1;
                o0.x = acc[ms][ns][0] + bv0; o0.y = acc[ms][ns][1] + bv1;
                o1.x = acc[ms][ns][2] + bv0; o1.y = acc[ms][ns][3] + bv1;
                *(float2*)(C + (size_t)row0 * Ntot + col) = o0;
                *(float2*)(C + (size_t)(row0 + 8) * Ntot + col) = o1;
            }
        }
    }
}

// ---------------- embedding --------------------------------------------------
__global__ void embed_k(const int* __restrict__ tok,
                        const float* __restrict__ emb,
                        float* __restrict__ out, int dec)
{
    int row = blockIdx.x;
    int tid = threadIdx.x;
    int t;
    if (dec) t = (row < B_SZ) ? 0 : tok[row - B_SZ];
    else     t = tok[row];
    out[row * H_SZ + tid] = emb[(size_t)t * H_SZ + tid];
}

// ---------------- clustered recurrence (unchanged from R11 pass) --------------
#define RWH      260
#define SM_W     0
#define SM_H0    (256 * 132)
#define SM_H1    (SM_H0 + 4 * RWH)
#define SM_RED   (SM_H1 + 4 * RWH)
#define SM_GB    (SM_RED + 512)
#define REC_SMEM_BYTES ((SM_GB + 512) * 4)

__device__ __forceinline__ float sigf(float x)   { return __fdividef(1.f, 1.f + __expf(-x)); }
__device__ __forceinline__ float tanh_f(float x) { float e = __expf(2.f * x); return __fdividef(e - 1.f, e + 1.f); }

__global__ void __launch_bounds__(256, 1) recl_k(
    const float* __restrict__ Gx, const float* __restrict__ Whh,
    const float* __restrict__ hinit, int hbcast,
    const float* __restrict__ cinit, int cbcast,
    float* __restrict__ Xout, float* __restrict__ hfin, float* __restrict__ cfin)
{
    extern __shared__ __align__(16) float sm[];
    int tid  = threadIdx.x;
    int rank = blockIdx.x & 7;
    int grp  = blockIdx.x >> 3;
    int row  = tid & 127, kh = tid >> 7;
    int q = row >> 5, wcol = row & 31;

    {
        int growL = q * 256 + 32 * rank + wcol;
        const float* wsrc = Whh + (size_t)growL * 256 + kh * 128;
#pragma unroll
        for (int v = 0; v < 32; v++) {
            float4 w = __ldg((const float4*)(wsrc + 4 * v));
            int k = kh * 128 + 4 * v;
            sm[SM_W + (k + 0) * 132 + row] = w.x;
            sm[SM_W + (k + 1) * 132 + row] = w.y;
            sm[SM_W + (k + 2) * 132 + row] = w.z;
            sm[SM_W + (k + 3) * 132 + row] = w.w;
        }
    }
    {
        int b = tid >> 6, k4 = tid & 63;
        float4 h4 = hbcast ? __ldg((const float4*)(hinit + 4 * k4))
                           : __ldg((const float4*)(hinit + (size_t)(4 * grp + b) * 256 + 4 * k4));
        *(float4*)(sm + SM_H0 + b * RWH + 4 * k4) = h4;
    }

    int ab = tid >> 5, acol = tid & 31;
    int b_glob = 4 * grp + ab;
    int col_glob = 32 * rank + acol;
    float creg = 0.f, hlast = 0.f;
    if (tid < 128)
        creg = cbcast ? cinit[col_glob] : cinit[(size_t)b_glob * 256 + col_glob];

    uint32_t peer[8];
    {
        uint32_t sb = smem_u32(sm);
#pragma unroll
        for (int p = 0; p < 8; p++) {
            uint32_t pa;
            asm("mapa.shared::cluster.u32 %0, %1, %2;" : "=r"(pa) : "r"(sb), "r"(p));
            peer[p] = pa;
        }
    }
    __syncthreads();

    for (int t = 0; t < T_STEPS; t++) {
        float gx0 = 0.f, gx1 = 0.f, gx2 = 0.f, gx3 = 0.f;
        if (tid < 128) {
            const float* gp = Gx + (size_t)(t * 64 + b_glob) * 1024 + col_glob;
            gx0 = __ldcg(gp);       gx1 = __ldcg(gp + 256);
            gx2 = __ldcg(gp + 512); gx3 = __ldcg(gp + 768);
        }
        if (t > 0)
            asm volatile("barrier.cluster.wait.aligned;" ::: "memory");

        const float* hc = sm + ((t & 1) ? SM_H1 : SM_H0);
        uint32_t hnOff  = (t & 1) ? SM_H0 : SM_H1;

        const float* wt = sm + SM_W + (kh * 128) * 132 + row;
        const float* hb = hc + kh * 128;
        float s0 = 0.f, s1 = 0.f, s2 = 0.f, s3 = 0.f;
#pragma unroll 8
        for (int k4 = 0; k4 < 32; k4++) {
            float w0 = wt[(4 * k4 + 0) * 132];
            float w1 = wt[(4 * k4 + 1) * 132];
            float w2 = wt[(4 * k4 + 2) * 132];
            float w3 = wt[(4 * k4 + 3) * 132];
            float4 h0 = *(const float4*)(hb + 0 * RWH + 4 * k4);
            float4 h1 = *(const float4*)(hb + 1 * RWH + 4 * k4);
            float4 h2 = *(const float4*)(hb + 2 * RWH + 4 * k4);
            float4 h3 = *(const float4*)(hb + 3 * RWH + 4 * k4);
            s0 += w0 * h0.x + w1 * h0.y + w2 * h0.z + w3 * h0.w;
            s1 += w0 * h1.x + w1 * h1.y + w2 * h1.z + w3 * h1.w;
            s2 += w0 * h2.x + w1 * h2.y + w2 * h2.z + w3 * h2.w;
            s3 += w0 * h3.x + w1 * h3.y + w2 * h3.z + w3 * h3.w;
        }
        if (kh == 1)
            *(float4*)(sm + SM_RED + row * 4) = make_float4(s0, s1, s2, s3);
        __syncthreads();
        if (kh == 0) {
            float4 o = *(const float4*)(sm + SM_RED + row * 4);
            sm[SM_GB + q * 128 + 0 * 32 + wcol] = s0 + o.x;
            sm[SM_GB + q * 128 + 1 * 32 + wcol] = s1 + o.y;
            sm[SM_GB + q * 128 + 2 * 32 + wcol] = s2 + o.z;
            sm[SM_GB + q * 128 + 3 * 32 + wcol] = s3 + o.w;
        }
        __syncthreads();

        if (tid < 128) {
            float iv = sm[SM_GB + 0 * 128 + ab * 32 + acol] + gx0;
            float fv = sm[SM_GB + 1 * 128 + ab * 32 + acol] + gx1;
            float gv = sm[SM_GB + 2 * 128 + ab * 32 + acol] + gx2;
            float ov = sm[SM_GB + 3 * 128 + ab * 32 + acol] + gx3;
            float cn = sigf(fv) * creg + sigf(iv) * tanh_f(gv);
            float hn = sigf(ov) * tanh_f(cn);
            creg = cn; hlast = hn;
            Xout[(size_t)(t * 64 + b_glob) * 256 + col_glob] = hn;
            uint32_t off = (hnOff + (uint32_t)ab * RWH + (uint32_t)col_glob) * 4u;
#pragma unroll
            for (int p = 0; p < 8; p++)
                asm volatile("st.shared::cluster.f32 [%0], %1;"
                             :: "r"(peer[p] + off), "f"(hn) : "memory");
        }
        asm volatile("barrier.cluster.arrive.aligned;" ::: "memory");
    }
    asm volatile("barrier.cluster.wait.aligned;" ::: "memory");

    if (tid < 128) {
        cfin[(size_t)b_glob * 256 + col_glob] = creg;
        hfin[(size_t)b_glob * 256 + col_glob] = hlast;
    }
}

// ---------------- row argmax over V (float4) ----------------------------------
__global__ void argmax_k(const float* __restrict__ logits, float* __restrict__ outIdx)
{
    int m = blockIdx.x;
    const float4* row = (const float4*)(logits + (size_t)m * V_SZ);
    int tid = threadIdx.x;
    float bv = -__int_as_float(0x7f800000);
    int bi = 0;
    for (int n4 = tid; n4 < V_SZ / 4; n4 += 256) {
        float4 v = row[n4];
        int base = n4 * 4;
        if (v.x > bv) { bv = v.x; bi = base; }
        if (v.y > bv) { bv = v.y; bi = base + 1; }
        if (v.z > bv) { bv = v.z; bi = base + 2; }
        if (v.w > bv) { bv = v.w; bi = base + 3; }
    }
    __shared__ float sv[256];
    __shared__ int   si[256];
    sv[tid] = bv; si[tid] = bi;
    __syncthreads();
    for (int s = 128; s > 0; s >>= 1) {
        if (tid < s) {
            float ov = sv[tid + s]; int oi = si[tid + s];
            if (ov > sv[tid] || (ov == sv[tid] && oi < si[tid])) { sv[tid] = ov; si[tid] = oi; }
        }
        __syncthreads();
    }
    if (tid == 0) outIdx[m] = (float)si[0];
}

// ---------------- cluster launch helper ---------------------------------------
static void launch_recl(const float* gx, const float* whh,
                        const float* hinit, int hbcast,
                        const float* cinit, int cbcast,
                        float* xout, float* hfin, float* cfin)
{
    cudaLaunchConfig_t cfg = {};
    cfg.gridDim = {128, 1, 1};
    cfg.blockDim = {256, 1, 1};
    cfg.dynamicSmemBytes = REC_SMEM_BYTES;
    cfg.stream = 0;
    cudaLaunchAttribute at[1];
    at[0].id = cudaLaunchAttributeClusterDimension;
    at[0].val.clusterDim = {8, 1, 1};
    cfg.attrs = at;
    cfg.numAttrs = 1;
    cudaLaunchKernelEx(&cfg, recl_k, gx, whh, hinit, hbcast, cinit, cbcast,
                       xout, hfin, cfin);
}

// ---------------- launch ------------------------------------------------------
extern "C" void kernel_launch(void* const* d_in, const int* in_sizes, int n_in,
                              void* d_out, int out_size)
{
    const int* inputs  = (const int*)d_in[0];
    const int* targets = (const int*)d_in[1];
    const float* enc_emb = (const float*)d_in[2];
    const float* enc_Wih = (const float*)d_in[3];
    const float* enc_Whh = (const float*)d_in[4];
    const float* enc_bih = (const float*)d_in[5];
    const float* enc_bhh = (const float*)d_in[6];
    const float* hidden0 = (const float*)d_in[7];
    const float* cell0   = (const float*)d_in[8];
    const float* dec_emb = (const float*)d_in[9];
    const float* dec_Wih = (const float*)d_in[10];
    const float* dec_Whh = (const float*)d_in[11];
    const float* dec_bih = (const float*)d_in[12];
    const float* dec_bhh = (const float*)d_in[13];
    const float* fc_W    = (const float*)d_in[14];
    const float* fc_b    = (const float*)d_in[15];
    float* out = (float*)d_out;

    float *bufA, *bufB, *gx, *hfin, *cfin;
    cudaGetSymbolAddress((void**)&bufA, g_bufA);
    cudaGetSymbolAddress((void**)&bufB, g_bufB);
    cudaGetSymbolAddress((void**)&gx,   g_gx);
    cudaGetSymbolAddress((void**)&hfin, g_hfin);
    cudaGetSymbolAddress((void**)&cfin, g_cfin);

    cudaFuncSetAttribute(recl_k, cudaFuncAttributeMaxDynamicSharedMemorySize, REC_SMEM_BYTES);
    cudaFuncSetAttribute(bgemm,  cudaFuncAttributeMaxDynamicSharedMemorySize, BG_SMEM);

    float* cur = bufA;
    float* nxt = bufB;

    // ---- encoder ----
    embed_k<<<M_TOT, 256>>>(inputs, enc_emb, cur, 0);
    for (int l = 0; l < 3; l++) {
        bgemm<<<148, 256, BG_SMEM>>>(cur, enc_Wih + (size_t)l * G_SZ * H_SZ,
                                     enc_bih + l * G_SZ, enc_bhh + l * G_SZ,
                                     gx, G_SZ);
        launch_recl(gx, enc_Whh + (size_t)l * G_SZ * H_SZ,
                    hidden0 + l * H_SZ, 1, cell0 + l * H_SZ, 1,
                    nxt, hfin + (size_t)l * B_SZ * H_SZ,
                    cfin + (size_t)l * B_SZ * H_SZ);
        float* tmp = cur; cur = nxt; nxt = tmp;
    }

    // ---- decoder (teacher forcing, shifted targets) ----
    embed_k<<<M_TOT, 256>>>(targets, dec_emb, cur, 1);
    for (int l = 0; l < 3; l++) {
        bgemm<<<148, 256, BG_SMEM>>>(cur, dec_Wih + (size_t)l * G_SZ * H_SZ,
                                     dec_bih + l * G_SZ, dec_bhh + l * G_SZ,
                                     gx, G_SZ);
        launch_recl(gx, dec_Whh + (size_t)l * G_SZ * H_SZ,
                    hfin + (size_t)l * B_SZ * H_SZ, 0,
                    cfin + (size_t)l * B_SZ * H_SZ, 0,
                    nxt, hfin + (size_t)l * B_SZ * H_SZ,
                    cfin + (size_t)l * B_SZ * H_SZ);
        float* tmp = cur; cur = nxt; nxt = tmp;
    }

    // ---- FC projection to vocab (bf16 2-split mma.sync) ----
    bgemm<<<148, 256, BG_SMEM>>>(cur, fc_W, fc_b, (const float*)nullptr, out, V_SZ);

    // ---- predicted words ----
    long long need = (long long)M_TOT * V_SZ + M_TOT;
    if ((long long)out_size >= need)
        argmax_k<<<M_TOT, 256>>>(out, out + (size_t)M_TOT * V_SZ);
}

// round 13
// speedup vs baseline: 1.0102x; 1.0102x over previous
#include <cuda_runtime.h>
#include <cuda_bf16.h>
#include <math.h>
#include <stdint.h>

#define T_STEPS 64
#define B_SZ    64
#define H_SZ    256
#define G_SZ    1024
#define M_TOT   4096      // T*B
#define V_SZ    32000

// ---------------- scratch ----------------------------------------------------
__device__ __align__(256) float g_bufA[M_TOT * H_SZ];
__device__ __align__(256) float g_bufB[M_TOT * H_SZ];
__device__ __align__(256) float g_gx[M_TOT * G_SZ];
__device__ __align__(256) float g_hfin[3 * B_SZ * H_SZ];
__device__ __align__(256) float g_cfin[3 * B_SZ * H_SZ];

// ================= bf16 2-split helpers ======================================
__device__ __forceinline__ uint32_t pack_bf2(unsigned short lo, unsigned short hi) {
    return ((uint32_t)hi << 16) | (uint32_t)lo;
}
__device__ __forceinline__ void split_bf(float a, unsigned short& h, unsigned short& l) {
    __nv_bfloat16 hb = __float2bfloat16_rn(a);
    float hf = __bfloat162float(hb);
    __nv_bfloat16 lb = __float2bfloat16_rn(a - hf);
    h = __bfloat16_as_ushort(hb);
    l = __bfloat16_as_ushort(lb);
}
__device__ __forceinline__ void split_store4(unsigned short* dhi, unsigned short* dlo, float4 a) {
    unsigned short h0, h1, h2, h3, l0, l1, l2, l3;
    split_bf(a.x, h0, l0); split_bf(a.y, h1, l1);
    split_bf(a.z, h2, l2); split_bf(a.w, h3, l3);
    uint2 hv; hv.x = pack_bf2(h0, h1); hv.y = pack_bf2(h2, h3);
    uint2 lv; lv.x = pack_bf2(l0, l1); lv.y = pack_bf2(l2, l3);
    *(uint2*)dhi = hv;
    *(uint2*)dlo = lv;
}

#define MMA_BF16(c, a, b) \
    asm volatile("mma.sync.aligned.m16n8k16.row.col.f32.bf16.bf16.f32 " \
        "{%0,%1,%2,%3}, {%4,%5,%6,%7}, {%8,%9}, {%0,%1,%2,%3};" \
        : "+f"((c)[0]), "+f"((c)[1]), "+f"((c)[2]), "+f"((c)[3]) \
        : "r"((a)[0]), "r"((a)[1]), "r"((a)[2]), "r"((a)[3]), \
          "r"((b)[0]), "r"((b)[1]))

__device__ __forceinline__ uint32_t smem_u32(const void* p) {
    uint32_t a;
    asm("{ .reg .u64 t; cvta.to.shared.u64 t, %1; cvt.u32.u64 %0, t; }" : "=r"(a) : "l"(p));
    return a;
}

// ================= bf16 2-split mma.sync GEMM ================================
// 512 threads / 16 warps (8M x 2N), warp tile 16x32. Same smem layout as the
// proven 256-thread version — double the resident warps per SMSP.
#define BG_LD   264
#define BG_AHI  0
#define BG_ALO  (128 * BG_LD)
#define BG_BHI  (2 * 128 * BG_LD)
#define BG_BLO  (2 * 128 * BG_LD + 64 * BG_LD)
#define BG_SMEM ((2 * 128 * BG_LD + 2 * 64 * BG_LD) * 2)

__global__ void __launch_bounds__(512, 1) bgemm(
    const float* __restrict__ A, const float* __restrict__ W,
    const float* __restrict__ b1, const float* __restrict__ b2,
    float* __restrict__ C, int Ntot)
{
    extern __shared__ __align__(16) unsigned short bsm[];

    int tid = threadIdx.x;
    int wid = tid >> 5, lane = tid & 31;
    int g = lane >> 2, t = lane & 3;
    int warpM = wid >> 1, warpN = wid & 1;     // 8 x 2 warps

    int nN = Ntot >> 6;
    int NT = nN << 5;
    int per = (NT + gridDim.x - 1) / gridDim.x;
    int tau0 = blockIdx.x * per;
    int tau1 = tau0 + per; if (tau1 > NT) tau1 = NT;
    int mPrev = -1;

    for (int tau = tau0; tau < tau1; tau++) {
        int mT = tau / nN, nT = tau - mT * nN;
        int m0 = mT << 7, n0 = nT << 6;

        __syncthreads();
        if (mT != mPrev) {
            const float* Ap = A + (size_t)m0 * 256;
#pragma unroll
            for (int v = 0; v < 16; v++) {
                int id = tid + 512 * v;            // 8192 float4 = 128 x 64
                int r = id >> 6, c4 = (id & 63) * 4;
                float4 a = __ldg((const float4*)(Ap + (size_t)r * 256 + c4));
                int hidx = r * BG_LD + c4;
                split_store4(bsm + BG_AHI + hidx, bsm + BG_ALO + hidx, a);
            }
            mPrev = mT;
        }
        {
            const float* Wp = W + (size_t)n0 * 256;
#pragma unroll
            for (int v = 0; v < 8; v++) {
                int id = tid + 512 * v;            // 4096 float4 = 64 x 64
                int r = id >> 6, c4 = (id & 63) * 4;
                float4 a = __ldg((const float4*)(Wp + (size_t)r * 256 + c4));
                int hidx = r * BG_LD + c4;
                split_store4(bsm + BG_BHI + hidx, bsm + BG_BLO + hidx, a);
            }
        }
        __syncthreads();

        float acc[4][4];
#pragma unroll
        for (int j = 0; j < 4; j++)
#pragma unroll
            for (int k = 0; k < 4; k++) acc[j][k] = 0.f;

        int aRow = warpM * 16;
        int bRow = warpN * 32;

#pragma unroll 2
        for (int kk = 0; kk < 256; kk += 16) {
            uint32_t ah[4], al[4];
            {
                int r0 = aRow + g;
                int i00 = r0 * BG_LD + 2 * t + kk;
                int i10 = (r0 + 8) * BG_LD + 2 * t + kk;
                ah[0] = *(const uint32_t*)(bsm + BG_AHI + i00);
                ah[1] = *(const uint32_t*)(bsm + BG_AHI + i10);
                ah[2] = *(const uint32_t*)(bsm + BG_AHI + i00 + 8);
                ah[3] = *(const uint32_t*)(bsm + BG_AHI + i10 + 8);
                al[0] = *(const uint32_t*)(bsm + BG_ALO + i00);
                al[1] = *(const uint32_t*)(bsm + BG_ALO + i10);
                al[2] = *(const uint32_t*)(bsm + BG_ALO + i00 + 8);
                al[3] = *(const uint32_t*)(bsm + BG_ALO + i10 + 8);
            }
            uint32_t bh[4][2], bl[4][2];
#pragma unroll
            for (int ns = 0; ns < 4; ns++) {
                int rw = bRow + ns * 8 + g;
                int ib = rw * BG_LD + 2 * t + kk;
                bh[ns][0] = *(const uint32_t*)(bsm + BG_BHI + ib);
                bh[ns][1] = *(const uint32_t*)(bsm + BG_BHI + ib + 8);
                bl[ns][0] = *(const uint32_t*)(bsm + BG_BLO + ib);
                bl[ns][1] = *(const uint32_t*)(bsm + BG_BLO + ib + 8);
            }
#pragma unroll
            for (int ns = 0; ns < 4; ns++) {
                MMA_BF16(acc[ns], ah, bh[ns]);
                MMA_BF16(acc[ns], ah, bl[ns]);
                MMA_BF16(acc[ns], al, bh[ns]);
            }
        }

        {
            int row0 = m0 + aRow + g;
#pragma unroll
            for (int ns = 0; ns < 4; ns++) {
                int col = n0 + bRow + ns * 8 + 2 * t;
                float bv0 = __ldg(b1 + col), bv1 = __ldg(b1 + col + 1);
                if (b2) { bv0 += __ldg(b2 + col); bv1 += __ldg(b2 + col + 1); }
                float2 o0, o1;
                o0.x = acc[ns][0] + bv0; o0.y = acc[ns][1] + bv1;
                o1.x = acc[ns][2] + bv0; o1.y = acc[ns][3] + bv1;
                *(float2*)(C + (size_t)row0 * Ntot + col) = o0;
                *(float2*)(C + (size_t)(row0 + 8) * Ntot + col) = o1;
            }
        }
    }
}

// ---------------- embedding --------------------------------------------------
__global__ void embed_k(const int* __restrict__ tok,
                        const float* __restrict__ emb,
                        float* __restrict__ out, int dec)
{
    int row = blockIdx.x;
    int tid = threadIdx.x;
    int t;
    if (dec) t = (row < B_SZ) ? 0 : tok[row - B_SZ];
    else     t = tok[row];
    out[row * H_SZ + tid] = emb[(size_t)t * H_SZ + tid];
}

// ---------------- clustered recurrence (unchanged from R11 pass) --------------
#define RWH      260
#define SM_W     0
#define SM_H0    (256 * 132)
#define SM_H1    (SM_H0 + 4 * RWH)
#define SM_RED   (SM_H1 + 4 * RWH)
#define SM_GB    (SM_RED + 512)
#define REC_SMEM_BYTES ((SM_GB + 512) * 4)

__device__ __forceinline__ float sigf(float x)   { return __fdividef(1.f, 1.f + __expf(-x)); }
__device__ __forceinline__ float tanh_f(float x) { float e = __expf(2.f * x); return __fdividef(e - 1.f, e + 1.f); }

__global__ void __launch_bounds__(256, 1) recl_k(
    const float* __restrict__ Gx, const float* __restrict__ Whh,
    const float* __restrict__ hinit, int hbcast,
    const float* __restrict__ cinit, int cbcast,
    float* __restrict__ Xout, float* __restrict__ hfin, float* __restrict__ cfin)
{
    extern __shared__ __align__(16) float sm[];
    int tid  = threadIdx.x;
    int rank = blockIdx.x & 7;
    int grp  = blockIdx.x >> 3;
    int row  = tid & 127, kh = tid >> 7;
    int q = row >> 5, wcol = row & 31;

    {
        int growL = q * 256 + 32 * rank + wcol;
        const float* wsrc = Whh + (size_t)growL * 256 + kh * 128;
#pragma unroll
        for (int v = 0; v < 32; v++) {
            float4 w = __ldg((const float4*)(wsrc + 4 * v));
            int k = kh * 128 + 4 * v;
            sm[SM_W + (k + 0) * 132 + row] = w.x;
            sm[SM_W + (k + 1) * 132 + row] = w.y;
            sm[SM_W + (k + 2) * 132 + row] = w.z;
            sm[SM_W + (k + 3) * 132 + row] = w.w;
        }
    }
    {
        int b = tid >> 6, k4 = tid & 63;
        float4 h4 = hbcast ? __ldg((const float4*)(hinit + 4 * k4))
                           : __ldg((const float4*)(hinit + (size_t)(4 * grp + b) * 256 + 4 * k4));
        *(float4*)(sm + SM_H0 + b * RWH + 4 * k4) = h4;
    }

    int ab = tid >> 5, acol = tid & 31;
    int b_glob = 4 * grp + ab;
    int col_glob = 32 * rank + acol;
    float creg = 0.f, hlast = 0.f;
    if (tid < 128)
        creg = cbcast ? cinit[col_glob] : cinit[(size_t)b_glob * 256 + col_glob];

    uint32_t peer[8];
    {
        uint32_t sb = smem_u32(sm);
#pragma unroll
        for (int p = 0; p < 8; p++) {
            uint32_t pa;
            asm("mapa.shared::cluster.u32 %0, %1, %2;" : "=r"(pa) : "r"(sb), "r"(p));
            peer[p] = pa;
        }
    }
    __syncthreads();

    for (int t = 0; t < T_STEPS; t++) {
        float gx0 = 0.f, gx1 = 0.f, gx2 = 0.f, gx3 = 0.f;
        if (tid < 128) {
            const float* gp = Gx + (size_t)(t * 64 + b_glob) * 1024 + col_glob;
            gx0 = __ldcg(gp);       gx1 = __ldcg(gp + 256);
            gx2 = __ldcg(gp + 512); gx3 = __ldcg(gp + 768);
        }
        if (t > 0)
            asm volatile("barrier.cluster.wait.aligned;" ::: "memory");

        const float* hc = sm + ((t & 1) ? SM_H1 : SM_H0);
        uint32_t hnOff  = (t & 1) ? SM_H0 : SM_H1;

        const float* wt = sm + SM_W + (kh * 128) * 132 + row;
        const float* hb = hc + kh * 128;
        float s0 = 0.f, s1 = 0.f, s2 = 0.f, s3 = 0.f;
#pragma unroll 8
        for (int k4 = 0; k4 < 32; k4++) {
            float w0 = wt[(4 * k4 + 0) * 132];
            float w1 = wt[(4 * k4 + 1) * 132];
            float w2 = wt[(4 * k4 + 2) * 132];
            float w3 = wt[(4 * k4 + 3) * 132];
            float4 h0 = *(const float4*)(hb + 0 * RWH + 4 * k4);
            float4 h1 = *(const float4*)(hb + 1 * RWH + 4 * k4);
            float4 h2 = *(const float4*)(hb + 2 * RWH + 4 * k4);
            float4 h3 = *(const float4*)(hb + 3 * RWH + 4 * k4);
            s0 += w0 * h0.x + w1 * h0.y + w2 * h0.z + w3 * h0.w;
            s1 += w0 * h1.x + w1 * h1.y + w2 * h1.z + w3 * h1.w;
            s2 += w0 * h2.x + w1 * h2.y + w2 * h2.z + w3 * h2.w;
            s3 += w0 * h3.x + w1 * h3.y + w2 * h3.z + w3 * h3.w;
        }
        if (kh == 1)
            *(float4*)(sm + SM_RED + row * 4) = make_float4(s0, s1, s2, s3);
        __syncthreads();
        if (kh == 0) {
            float4 o = *(const float4*)(sm + SM_RED + row * 4);
            sm[SM_GB + q * 128 + 0 * 32 + wcol] = s0 + o.x;
            sm[SM_GB + q * 128 + 1 * 32 + wcol] = s1 + o.y;
            sm[SM_GB + q * 128 + 2 * 32 + wcol] = s2 + o.z;
            sm[SM_GB + q * 128 + 3 * 32 + wcol] = s3 + o.w;
        }
        __syncthreads();

        if (tid < 128) {
            float iv = sm[SM_GB + 0 * 128 + ab * 32 + acol] + gx0;
            float fv = sm[SM_GB + 1 * 128 + ab * 32 + acol] + gx1;
            float gv = sm[SM_GB + 2 * 128 + ab * 32 + acol] + gx2;
            float ov = sm[SM_GB + 3 * 128 + ab * 32 + acol] + gx3;
            float cn = sigf(fv) * creg + sigf(iv) * tanh_f(gv);
            float hn = sigf(ov) * tanh_f(cn);
            creg = cn; hlast = hn;
            Xout[(size_t)(t * 64 + b_glob) * 256 + col_glob] = hn;
            uint32_t off = (hnOff + (uint32_t)ab * RWH + (uint32_t)col_glob) * 4u;
#pragma unroll
            for (int p = 0; p < 8; p++)
                asm volatile("st.shared::cluster.f32 [%0], %1;"
                             :: "r"(peer[p] + off), "f"(hn) : "memory");
        }
        asm volatile("barrier.cluster.arrive.aligned;" ::: "memory");
    }
    asm volatile("barrier.cluster.wait.aligned;" ::: "memory");

    if (tid < 128) {
        cfin[(size_t)b_glob * 256 + col_glob] = creg;
        hfin[(size_t)b_glob * 256 + col_glob] = hlast;
    }
}

// ---------------- row argmax over V (float4) ----------------------------------
__global__ void argmax_k(const float* __restrict__ logits, float* __restrict__ outIdx)
{
    int m = blockIdx.x;
    const float4* row = (const float4*)(logits + (size_t)m * V_SZ);
    int tid = threadIdx.x;
    float bv = -__int_as_float(0x7f800000);
    int bi = 0;
    for (int n4 = tid; n4 < V_SZ / 4; n4 += 256) {
        float4 v = row[n4];
        int base = n4 * 4;
        if (v.x > bv) { bv = v.x; bi = base; }
        if (v.y > bv) { bv = v.y; bi = base + 1; }
        if (v.z > bv) { bv = v.z; bi = base + 2; }
        if (v.w > bv) { bv = v.w; bi = base + 3; }
    }
    __shared__ float sv[256];
    __shared__ int   si[256];
    sv[tid] = bv; si[tid] = bi;
    __syncthreads();
    for (int s = 128; s > 0; s >>= 1) {
        if (tid < s) {
            float ov = sv[tid + s]; int oi = si[tid + s];
            if (ov > sv[tid] || (ov == sv[tid] && oi < si[tid])) { sv[tid] = ov; si[tid] = oi; }
        }
        __syncthreads();
    }
    if (tid == 0) outIdx[m] = (float)si[0];
}

// ---------------- cluster launch helper ---------------------------------------
static void launch_recl(const float* gx, const float* whh,
                        const float* hinit, int hbcast,
                        const float* cinit, int cbcast,
                        float* xout, float* hfin, float* cfin)
{
    cudaLaunchConfig_t cfg = {};
    cfg.gridDim = {128, 1, 1};
    cfg.blockDim = {256, 1, 1};
    cfg.dynamicSmemBytes = REC_SMEM_BYTES;
    cfg.stream = 0;
    cudaLaunchAttribute at[1];
    at[0].id = cudaLaunchAttributeClusterDimension;
    at[0].val.clusterDim = {8, 1, 1};
    cfg.attrs = at;
    cfg.numAttrs = 1;
    cudaLaunchKernelEx(&cfg, recl_k, gx, whh, hinit, hbcast, cinit, cbcast,
                       xout, hfin, cfin);
}

// ---------------- launch ------------------------------------------------------
extern "C" void kernel_launch(void* const* d_in, const int* in_sizes, int n_in,
                              void* d_out, int out_size)
{
    const int* inputs  = (const int*)d_in[0];
    const int* targets = (const int*)d_in[1];
    const float* enc_emb = (const float*)d_in[2];
    const float* enc_Wih = (const float*)d_in[3];
    const float* enc_Whh = (const float*)d_in[4];
    const float* enc_bih = (const float*)d_in[5];
    const float* enc_bhh = (const float*)d_in[6];
    const float* hidden0 = (const float*)d_in[7];
    const float* cell0   = (const float*)d_in[8];
    const float* dec_emb = (const float*)d_in[9];
    const float* dec_Wih = (const float*)d_in[10];
    const float* dec_Whh = (const float*)d_in[11];
    const float* dec_bih = (const float*)d_in[12];
    const float* dec_bhh = (const float*)d_in[13];
    const float* fc_W    = (const float*)d_in[14];
    const float* fc_b    = (const float*)d_in[15];
    float* out = (float*)d_out;

    float *bufA, *bufB, *gx, *hfin, *cfin;
    cudaGetSymbolAddress((void**)&bufA, g_bufA);
    cudaGetSymbolAddress((void**)&bufB, g_bufB);
    cudaGetSymbolAddress((void**)&gx,   g_gx);
    cudaGetSymbolAddress((void**)&hfin, g_hfin);
    cudaGetSymbolAddress((void**)&cfin, g_cfin);

    cudaFuncSetAttribute(recl_k, cudaFuncAttributeMaxDynamicSharedMemorySize, REC_SMEM_BYTES);
    cudaFuncSetAttribute(bgemm,  cudaFuncAttributeMaxDynamicSharedMemorySize, BG_SMEM);

    float* cur = bufA;
    float* nxt = bufB;

    // ---- encoder ----
    embed_k<<<M_TOT, 256>>>(inputs, enc_emb, cur, 0);
    for (int l = 0; l < 3; l++) {
        bgemm<<<148, 512, BG_SMEM>>>(cur, enc_Wih + (size_t)l * G_SZ * H_SZ,
                                     enc_bih + l * G_SZ, enc_bhh + l * G_SZ,
                                     gx, G_SZ);
        launch_recl(gx, enc_Whh + (size_t)l * G_SZ * H_SZ,
                    hidden0 + l * H_SZ, 1, cell0 + l * H_SZ, 1,
                    nxt, hfin + (size_t)l * B_SZ * H_SZ,
                    cfin + (size_t)l * B_SZ * H_SZ);
        float* tmp = cur; cur = nxt; nxt = tmp;
    }

    // ---- decoder (teacher forcing, shifted targets) ----
    embed_k<<<M_TOT, 256>>>(targets, dec_emb, cur, 1);
    for (int l = 0; l < 3; l++) {
        bgemm<<<148, 512, BG_SMEM>>>(cur, dec_Wih + (size_t)l * G_SZ * H_SZ,
                                     dec_bih + l * G_SZ, dec_bhh + l * G_SZ,
                                     gx, G_SZ);
        launch_recl(gx, dec_Whh + (size_t)l * G_SZ * H_SZ,
                    hfin + (size_t)l * B_SZ * H_SZ, 0,
                    cfin + (size_t)l * B_SZ * H_SZ, 0,
                    nxt, hfin + (size_t)l * B_SZ * H_SZ,
                    cfin + (size_t)l * B_SZ * H_SZ);
        float* tmp = cur; cur = nxt; nxt = tmp;
    }

    // ---- FC projection to vocab (bf16 2-split mma.sync) ----
    bgemm<<<148, 512, BG_SMEM>>>(cur, fc_W, fc_b, (const float*)nullptr, out, V_SZ);

    // ---- predicted words ----
    long long need = (long long)M_TOT * V_SZ + M_TOT;
    if ((long long)out_size >= need)
        argmax_k<<<M_TOT, 256>>>(out, out + (size_t)M_TOT * V_SZ);
}

// round 15
// speedup vs baseline: 1.0230x; 1.0127x over previous
#include <cuda_runtime.h>
#include <cuda_bf16.h>
#include <math.h>
#include <stdint.h>

#define T_STEPS 64
#define B_SZ    64
#define H_SZ    256
#define G_SZ    1024
#define M_TOT   4096      // T*B
#define V_SZ    32000

// ---------------- scratch ----------------------------------------------------
__device__ __align__(256) float g_bufA[M_TOT * H_SZ];
__device__ __align__(256) float g_bufB[M_TOT * H_SZ];
__device__ __align__(256) float g_gx[M_TOT * G_SZ];
__device__ __align__(256) float g_hfin[3 * B_SZ * H_SZ];
__device__ __align__(256) float g_cfin[3 * B_SZ * H_SZ];

// ================= bf16 2-split helpers ======================================
__device__ __forceinline__ uint32_t pack_bf2(unsigned short lo, unsigned short hi) {
    return ((uint32_t)hi << 16) | (uint32_t)lo;
}
__device__ __forceinline__ void split_bf(float a, unsigned short& h, unsigned short& l) {
    __nv_bfloat16 hb = __float2bfloat16_rn(a);
    float hf = __bfloat162float(hb);
    __nv_bfloat16 lb = __float2bfloat16_rn(a - hf);
    h = __bfloat16_as_ushort(hb);
    l = __bfloat16_as_ushort(lb);
}
__device__ __forceinline__ void split_store4(unsigned short* dhi, unsigned short* dlo, float4 a) {
    unsigned short h0, h1, h2, h3, l0, l1, l2, l3;
    split_bf(a.x, h0, l0); split_bf(a.y, h1, l1);
    split_bf(a.z, h2, l2); split_bf(a.w, h3, l3);
    uint2 hv; hv.x = pack_bf2(h0, h1); hv.y = pack_bf2(h2, h3);
    uint2 lv; lv.x = pack_bf2(l0, l1); lv.y = pack_bf2(l2, l3);
    *(uint2*)dhi = hv;
    *(uint2*)dlo = lv;
}

#define MMA_BF16(c, a, b) \
    asm volatile("mma.sync.aligned.m16n8k16.row.col.f32.bf16.bf16.f32 " \
        "{%0,%1,%2,%3}, {%4,%5,%6,%7}, {%8,%9}, {%0,%1,%2,%3};" \
        : "+f"((c)[0]), "+f"((c)[1]), "+f"((c)[2]), "+f"((c)[3]) \
        : "r"((a)[0]), "r"((a)[1]), "r"((a)[2]), "r"((a)[3]), \
          "r"((b)[0]), "r"((b)[1]))

#define LDSM_X4(r, addr) \
    asm volatile("ldmatrix.sync.aligned.m8n8.x4.shared.b16 {%0,%1,%2,%3}, [%4];" \
        : "=r"((r)[0]), "=r"((r)[1]), "=r"((r)[2]), "=r"((r)[3]) : "r"(addr))

__device__ __forceinline__ uint32_t smem_u32(const void* p) {
    uint32_t a;
    asm("{ .reg .u64 t; cvta.to.shared.u64 t, %1; cvt.u32.u64 %0, t; }" : "=r"(a) : "l"(p));
    return a;
}

// ================= bf16 2-split mma.sync GEMM ================================
// 512 threads / 16 warps (8M x 2N), warp tile 16x32, ldmatrix fragment loads.
#define BG_LD   264
#define BG_AHI  0
#define BG_ALO  (128 * BG_LD)
#define BG_BHI  (2 * 128 * BG_LD)
#define BG_BLO  (2 * 128 * BG_LD + 64 * BG_LD)
#define BG_SMEM ((2 * 128 * BG_LD + 2 * 64 * BG_LD) * 2)

__global__ void __launch_bounds__(512, 1) bgemm(
    const float* __restrict__ A, const float* __restrict__ W,
    const float* __restrict__ b1, const float* __restrict__ b2,
    float* __restrict__ C, int Ntot)
{
    extern __shared__ __align__(16) unsigned short bsm[];

    int tid = threadIdx.x;
    int wid = tid >> 5, lane = tid & 31;
    int g = lane >> 2, t = lane & 3;
    int warpM = wid >> 1, warpN = wid & 1;     // 8 x 2 warps

    int nN = Ntot >> 6;
    int NT = nN << 5;
    int per = (NT + gridDim.x - 1) / gridDim.x;
    int tau0 = blockIdx.x * per;
    int tau1 = tau0 + per; if (tau1 > NT) tau1 = NT;
    int mPrev = -1;

    uint32_t sbase = smem_u32(bsm);
    int aRow = warpM * 16;
    int bRow = warpN * 32;
    // ldmatrix per-lane base offsets (in halves)
    int aOff = (aRow + (lane & 15)) * BG_LD + ((lane >> 4) << 3);
    int bRowLane = bRow + (lane >> 4) * 8 + (lane & 7);
    int bColBlk = ((lane >> 3) & 1) << 3;
    int bOff01 = bRowLane * BG_LD + bColBlk;          // n-slices 0,1
    int bOff23 = (bRowLane + 16) * BG_LD + bColBlk;   // n-slices 2,3

    for (int tau = tau0; tau < tau1; tau++) {
        int mT = tau / nN, nT = tau - mT * nN;
        int m0 = mT << 7, n0 = nT << 6;

        __syncthreads();
        if (mT != mPrev) {
            const float* Ap = A + (size_t)m0 * 256;
#pragma unroll
            for (int v = 0; v < 16; v++) {
                int id = tid + 512 * v;            // 8192 float4 = 128 x 64
                int r = id >> 6, c4 = (id & 63) * 4;
                float4 a = __ldg((const float4*)(Ap + (size_t)r * 256 + c4));
                int hidx = r * BG_LD + c4;
                split_store4(bsm + BG_AHI + hidx, bsm + BG_ALO + hidx, a);
            }
            mPrev = mT;
        }
        {
            const float* Wp = W + (size_t)n0 * 256;
#pragma unroll
            for (int v = 0; v < 8; v++) {
                int id = tid + 512 * v;            // 4096 float4 = 64 x 64
                int r = id >> 6, c4 = (id & 63) * 4;
                float4 a = __ldg((const float4*)(Wp + (size_t)r * 256 + c4));
                int hidx = r * BG_LD + c4;
                split_store4(bsm + BG_BHI + hidx, bsm + BG_BLO + hidx, a);
            }
        }
        __syncthreads();

        float acc[4][4];
#pragma unroll
        for (int j = 0; j < 4; j++)
#pragma unroll
            for (int k = 0; k < 4; k++) acc[j][k] = 0.f;

#pragma unroll 2
        for (int kk = 0; kk < 256; kk += 16) {
            uint32_t ah[4], al[4];
            LDSM_X4(ah, sbase + (uint32_t)(BG_AHI + aOff + kk) * 2);
            LDSM_X4(al, sbase + (uint32_t)(BG_ALO + aOff + kk) * 2);
            uint32_t bh01[4], bh23[4], bl01[4], bl23[4];
            LDSM_X4(bh01, sbase + (uint32_t)(BG_BHI + bOff01 + kk) * 2);
            LDSM_X4(bh23, sbase + (uint32_t)(BG_BHI + bOff23 + kk) * 2);
            LDSM_X4(bl01, sbase + (uint32_t)(BG_BLO + bOff01 + kk) * 2);
            LDSM_X4(bl23, sbase + (uint32_t)(BG_BLO + bOff23 + kk) * 2);

            MMA_BF16(acc[0], ah, &bh01[0]);
            MMA_BF16(acc[1], ah, &bh01[2]);
            MMA_BF16(acc[2], ah, &bh23[0]);
            MMA_BF16(acc[3], ah, &bh23[2]);
            MMA_BF16(acc[0], ah, &bl01[0]);
            MMA_BF16(acc[1], ah, &bl01[2]);
            MMA_BF16(acc[2], ah, &bl23[0]);
            MMA_BF16(acc[3], ah, &bl23[2]);
            MMA_BF16(acc[0], al, &bh01[0]);
            MMA_BF16(acc[1], al, &bh01[2]);
            MMA_BF16(acc[2], al, &bh23[0]);
            MMA_BF16(acc[3], al, &bh23[2]);
        }

        {
            int row0 = m0 + aRow + g;
#pragma unroll
            for (int ns = 0; ns < 4; ns++) {
                int col = n0 + bRow + ns * 8 + 2 * t;
                float bv0 = __ldg(b1 + col), bv1 = __ldg(b1 + col + 1);
                if (b2) { bv0 += __ldg(b2 + col); bv1 += __ldg(b2 + col + 1); }
                float2 o0, o1;
                o0.x = acc[ns][0] + bv0; o0.y = acc[ns][1] + bv1;
                o1.x = acc[ns][2] + bv0; o1.y = acc[ns][3] + bv1;
                *(float2*)(C + (size_t)row0 * Ntot + col) = o0;
                *(float2*)(C + (size_t)(row0 + 8) * Ntot + col) = o1;
            }
        }
    }
}

// ---------------- embedding --------------------------------------------------
__global__ void embed_k(const int* __restrict__ tok,
                        const float* __restrict__ emb,
                        float* __restrict__ out, int dec)
{
    int row = blockIdx.x;
    int tid = threadIdx.x;
    int t;
    if (dec) t = (row < B_SZ) ? 0 : tok[row - B_SZ];
    else     t = tok[row];
    out[row * H_SZ + tid] = emb[(size_t)t * H_SZ + tid];
}

// ---------------- clustered recurrence (unchanged from R11 pass) --------------
#define RWH      260
#define SM_W     0
#define SM_H0    (256 * 132)
#define SM_H1    (SM_H0 + 4 * RWH)
#define SM_RED   (SM_H1 + 4 * RWH)
#define SM_GB    (SM_RED + 512)
#define REC_SMEM_BYTES ((SM_GB + 512) * 4)

__device__ __forceinline__ float sigf(float x)   { return __fdividef(1.f, 1.f + __expf(-x)); }
__device__ __forceinline__ float tanh_f(float x) { float e = __expf(2.f * x); return __fdividef(e - 1.f, e + 1.f); }

__global__ void __launch_bounds__(256, 1) recl_k(
    const float* __restrict__ Gx, const float* __restrict__ Whh,
    const float* __restrict__ hinit, int hbcast,
    const float* __restrict__ cinit, int cbcast,
    float* __restrict__ Xout, float* __restrict__ hfin, float* __restrict__ cfin)
{
    extern __shared__ __align__(16) float sm[];
    int tid  = threadIdx.x;
    int rank = blockIdx.x & 7;
    int grp  = blockIdx.x >> 3;
    int row  = tid & 127, kh = tid >> 7;
    int q = row >> 5, wcol = row & 31;

    {
        int growL = q * 256 + 32 * rank + wcol;
        const float* wsrc = Whh + (size_t)growL * 256 + kh * 128;
#pragma unroll
        for (int v = 0; v < 32; v++) {
            float4 w = __ldg((const float4*)(wsrc + 4 * v));
            int k = kh * 128 + 4 * v;
            sm[SM_W + (k + 0) * 132 + row] = w.x;
            sm[SM_W + (k + 1) * 132 + row] = w.y;
            sm[SM_W + (k + 2) * 132 + row] = w.z;
            sm[SM_W + (k + 3) * 132 + row] = w.w;
        }
    }
    {
        int b = tid >> 6, k4 = tid & 63;
        float4 h4 = hbcast ? __ldg((const float4*)(hinit + 4 * k4))
                           : __ldg((const float4*)(hinit + (size_t)(4 * grp + b) * 256 + 4 * k4));
        *(float4*)(sm + SM_H0 + b * RWH + 4 * k4) = h4;
    }

    int ab = tid >> 5, acol = tid & 31;
    int b_glob = 4 * grp + ab;
    int col_glob = 32 * rank + acol;
    float creg = 0.f, hlast = 0.f;
    if (tid < 128)
        creg = cbcast ? cinit[col_glob] : cinit[(size_t)b_glob * 256 + col_glob];

    uint32_t peer[8];
    {
        uint32_t sb = smem_u32(sm);
#pragma unroll
        for (int p = 0; p < 8; p++) {
            uint32_t pa;
            asm("mapa.shared::cluster.u32 %0, %1, %2;" : "=r"(pa) : "r"(sb), "r"(p));
            peer[p] = pa;
        }
    }
    __syncthreads();

    for (int t = 0; t < T_STEPS; t++) {
        float gx0 = 0.f, gx1 = 0.f, gx2 = 0.f, gx3 = 0.f;
        if (tid < 128) {
            const float* gp = Gx + (size_t)(t * 64 + b_glob) * 1024 + col_glob;
            gx0 = __ldcg(gp);       gx1 = __ldcg(gp + 256);
            gx2 = __ldcg(gp + 512); gx3 = __ldcg(gp + 768);
        }
        if (t > 0)
            asm volatile("barrier.cluster.wait.aligned;" ::: "memory");

        const float* hc = sm + ((t & 1) ? SM_H1 : SM_H0);
        uint32_t hnOff  = (t & 1) ? SM_H0 : SM_H1;

        const float* wt = sm + SM_W + (kh * 128) * 132 + row;
        const float* hb = hc + kh * 128;
        float s0 = 0.f, s1 = 0.f, s2 = 0.f, s3 = 0.f;
#pragma unroll 8
        for (int k4 = 0; k4 < 32; k4++) {
            float w0 = wt[(4 * k4 + 0) * 132];
            float w1 = wt[(4 * k4 + 1) * 132];
            float w2 = wt[(4 * k4 + 2) * 132];
            float w3 = wt[(4 * k4 + 3) * 132];
            float4 h0 = *(const float4*)(hb + 0 * RWH + 4 * k4);
            float4 h1 = *(const float4*)(hb + 1 * RWH + 4 * k4);
            float4 h2 = *(const float4*)(hb + 2 * RWH + 4 * k4);
            float4 h3 = *(const float4*)(hb + 3 * RWH + 4 * k4);
            s0 += w0 * h0.x + w1 * h0.y + w2 * h0.z + w3 * h0.w;
            s1 += w0 * h1.x + w1 * h1.y + w2 * h1.z + w3 * h1.w;
            s2 += w0 * h2.x + w1 * h2.y + w2 * h2.z + w3 * h2.w;
            s3 += w0 * h3.x + w1 * h3.y + w2 * h3.z + w3 * h3.w;
        }
        if (kh == 1)
            *(float4*)(sm + SM_RED + row * 4) = make_float4(s0, s1, s2, s3);
        __syncthreads();
        if (kh == 0) {
            float4 o = *(const float4*)(sm + SM_RED + row * 4);
            sm[SM_GB + q * 128 + 0 * 32 + wcol] = s0 + o.x;
            sm[SM_GB + q * 128 + 1 * 32 + wcol] = s1 + o.y;
            sm[SM_GB + q * 128 + 2 * 32 + wcol] = s2 + o.z;
            sm[SM_GB + q * 128 + 3 * 32 + wcol] = s3 + o.w;
        }
        __syncthreads();

        if (tid < 128) {
            float iv = sm[SM_GB + 0 * 128 + ab * 32 + acol] + gx0;
            float fv = sm[SM_GB + 1 * 128 + ab * 32 + acol] + gx1;
            float gv = sm[SM_GB + 2 * 128 + ab * 32 + acol] + gx2;
            float ov = sm[SM_GB + 3 * 128 + ab * 32 + acol] + gx3;
            float cn = sigf(fv) * creg + sigf(iv) * tanh_f(gv);
            float hn = sigf(ov) * tanh_f(cn);
            creg = cn; hlast = hn;
            Xout[(size_t)(t * 64 + b_glob) * 256 + col_glob] = hn;
            uint32_t off = (hnOff + (uint32_t)ab * RWH + (uint32_t)col_glob) * 4u;
#pragma unroll
            for (int p = 0; p < 8; p++)
                asm volatile("st.shared::cluster.f32 [%0], %1;"
                             :: "r"(peer[p] + off), "f"(hn) : "memory");
        }
        asm volatile("barrier.cluster.arrive.aligned;" ::: "memory");
    }
    asm volatile("barrier.cluster.wait.aligned;" ::: "memory");

    if (tid < 128) {
        cfin[(size_t)b_glob * 256 + col_glob] = creg;
        hfin[(size_t)b_glob * 256 + col_glob] = hlast;
    }
}

// ---------------- row argmax over V (float4) ----------------------------------
__global__ void argmax_k(const float* __restrict__ logits, float* __restrict__ outIdx)
{
    int m = blockIdx.x;
    const float4* row = (const float4*)(logits + (size_t)m * V_SZ);
    int tid = threadIdx.x;
    float bv = -__int_as_float(0x7f800000);
    int bi = 0;
    for (int n4 = tid; n4 < V_SZ / 4; n4 += 256) {
        float4 v = row[n4];
        int base = n4 * 4;
        if (v.x > bv) { bv = v.x; bi = base; }
        if (v.y > bv) { bv = v.y; bi = base + 1; }
        if (v.z > bv) { bv = v.z; bi = base + 2; }
        if (v.w > bv) { bv = v.w; bi = base + 3; }
    }
    __shared__ float sv[256];
    __shared__ int   si[256];
    sv[tid] = bv; si[tid] = bi;
    __syncthreads();
    for (int s = 128; s > 0; s >>= 1) {
        if (tid < s) {
            float ov = sv[tid + s]; int oi = si[tid + s];
            if (ov > sv[tid] || (ov == sv[tid] && oi < si[tid])) { sv[tid] = ov; si[tid] = oi; }
        }
        __syncthreads();
    }
    if (tid == 0) outIdx[m] = (float)si[0];
}

// ---------------- cluster launch helper ---------------------------------------
static void launch_recl(const float* gx, const float* whh,
                        const float* hinit, int hbcast,
                        const float* cinit, int cbcast,
                        float* xout, float* hfin, float* cfin)
{
    cudaLaunchConfig_t cfg = {};
    cfg.gridDim = {128, 1, 1};
    cfg.blockDim = {256, 1, 1};
    cfg.dynamicSmemBytes = REC_SMEM_BYTES;
    cfg.stream = 0;
    cudaLaunchAttribute at[1];
    at[0].id = cudaLaunchAttributeClusterDimension;
    at[0].val.clusterDim = {8, 1, 1};
    cfg.attrs = at;
    cfg.numAttrs = 1;
    cudaLaunchKernelEx(&cfg, recl_k, gx, whh, hinit, hbcast, cinit, cbcast,
                       xout, hfin, cfin);
}

// ---------------- launch ------------------------------------------------------
extern "C" void kernel_launch(void* const* d_in, const int* in_sizes, int n_in,
                              void* d_out, int out_size)
{
    const int* inputs  = (const int*)d_in[0];
    const int* targets = (const int*)d_in[1];
    const float* enc_emb = (const float*)d_in[2];
    const float* enc_Wih = (const float*)d_in[3];
    const float* enc_Whh = (const float*)d_in[4];
    const float* enc_bih = (const float*)d_in[5];
    const float* enc_bhh = (const float*)d_in[6];
    const float* hidden0 = (const float*)d_in[7];
    const float* cell0   = (const float*)d_in[8];
    const float* dec_emb = (const float*)d_in[9];
    const float* dec_Wih = (const float*)d_in[10];
    const float* dec_Whh = (const float*)d_in[11];
    const float* dec_bih = (const float*)d_in[12];
    const float* dec_bhh = (const float*)d_in[13];
    const float* fc_W    = (const float*)d_in[14];
    const float* fc_b    = (const float*)d_in[15];
    float* out = (float*)d_out;

    float *bufA, *bufB, *gx, *hfin, *cfin;
    cudaGetSymbolAddress((void**)&bufA, g_bufA);
    cudaGetSymbolAddress((void**)&bufB, g_bufB);
    cudaGetSymbolAddress((void**)&gx,   g_gx);
    cudaGetSymbolAddress((void**)&hfin, g_hfin);
    cudaGetSymbolAddress((void**)&cfin, g_cfin);

    cudaFuncSetAttribute(recl_k, cudaFuncAttributeMaxDynamicSharedMemorySize, REC_SMEM_BYTES);
    cudaFuncSetAttribute(bgemm,  cudaFuncAttributeMaxDynamicSharedMemorySize, BG_SMEM);

    float* cur = bufA;
    float* nxt = bufB;

    // ---- encoder ----
    embed_k<<<M_TOT, 256>>>(inputs, enc_emb, cur, 0);
    for (int l = 0; l < 3; l++) {
        bgemm<<<148, 512, BG_SMEM>>>(cur, enc_Wih + (size_t)l * G_SZ * H_SZ,
                                     enc_bih + l * G_SZ, enc_bhh + l * G_SZ,
                                     gx, G_SZ);
        launch_recl(gx, enc_Whh + (size_t)l * G_SZ * H_SZ,
                    hidden0 + l * H_SZ, 1, cell0 + l * H_SZ, 1,
                    nxt, hfin + (size_t)l * B_SZ * H_SZ,
                    cfin + (size_t)l * B_SZ * H_SZ);
        float* tmp = cur; cur = nxt; nxt = tmp;
    }

    // ---- decoder (teacher forcing, shifted targets) ----
    embed_k<<<M_TOT, 256>>>(targets, dec_emb, cur, 1);
    for (int l = 0; l < 3; l++) {
        bgemm<<<148, 512, BG_SMEM>>>(cur, dec_Wih + (size_t)l * G_SZ * H_SZ,
                                     dec_bih + l * G_SZ, dec_bhh + l * G_SZ,
                                     gx, G_SZ);
        launch_recl(gx, dec_Whh + (size_t)l * G_SZ * H_SZ,
                    hfin + (size_t)l * B_SZ * H_SZ, 0,
                    cfin + (size_t)l * B_SZ * H_SZ, 0,
                    nxt, hfin + (size_t)l * B_SZ * H_SZ,
                    cfin + (size_t)l * B_SZ * H_SZ);
        float* tmp = cur; cur = nxt; nxt = tmp;
    }

    // ---- FC projection to vocab (bf16 2-split mma.sync) ----
    bgemm<<<148, 512, BG_SMEM>>>(cur, fc_W, fc_b, (const float*)nullptr, out, V_SZ);

    // ---- predicted words ----
    long long need = (long long)M_TOT * V_SZ + M_TOT;
    if ((long long)out_size >= need)
        argmax_k<<<M_TOT, 256>>>(out, out + (size_t)M_TOT * V_SZ);
}

// round 16
// speedup vs baseline: 1.2915x; 1.2624x over previous
#include <cuda_runtime.h>
#include <cuda_bf16.h>
#include <math.h>
#include <stdint.h>

#define T_STEPS 64
#define B_SZ    64
#define H_SZ    256
#define G_SZ    1024
#define M_TOT   4096      // T*B
#define V_SZ    32000

// ---------------- scratch ----------------------------------------------------
__device__ __align__(256) float g_bufA[M_TOT * H_SZ];
__device__ __align__(256) float g_bufB[M_TOT * H_SZ];
__device__ __align__(256) float g_gx[M_TOT * G_SZ];
__device__ __align__(256) float g_hfin[3 * B_SZ * H_SZ];
__device__ __align__(256) float g_cfin[3 * B_SZ * H_SZ];

// ================= bf16 2-split helpers ======================================
__device__ __forceinline__ uint32_t pack_bf2(unsigned short lo, unsigned short hi) {
    return ((uint32_t)hi << 16) | (uint32_t)lo;
}
__device__ __forceinline__ void split_bf(float a, unsigned short& h, unsigned short& l) {
    __nv_bfloat16 hb = __float2bfloat16_rn(a);
    float hf = __bfloat162float(hb);
    __nv_bfloat16 lb = __float2bfloat16_rn(a - hf);
    h = __bfloat16_as_ushort(hb);
    l = __bfloat16_as_ushort(lb);
}
__device__ __forceinline__ void split_store4(unsigned short* dhi, unsigned short* dlo, float4 a) {
    unsigned short h0, h1, h2, h3, l0, l1, l2, l3;
    split_bf(a.x, h0, l0); split_bf(a.y, h1, l1);
    split_bf(a.z, h2, l2); split_bf(a.w, h3, l3);
    uint2 hv; hv.x = pack_bf2(h0, h1); hv.y = pack_bf2(h2, h3);
    uint2 lv; lv.x = pack_bf2(l0, l1); lv.y = pack_bf2(l2, l3);
    *(uint2*)dhi = hv;
    *(uint2*)dlo = lv;
}

#define MMA_BF16(c, a, b) \
    asm volatile("mma.sync.aligned.m16n8k16.row.col.f32.bf16.bf16.f32 " \
        "{%0,%1,%2,%3}, {%4,%5,%6,%7}, {%8,%9}, {%0,%1,%2,%3};" \
        : "+f"((c)[0]), "+f"((c)[1]), "+f"((c)[2]), "+f"((c)[3]) \
        : "r"((a)[0]), "r"((a)[1]), "r"((a)[2]), "r"((a)[3]), \
          "r"((b)[0]), "r"((b)[1]))

#define LDSM_X4(r, addr) \
    asm volatile("ldmatrix.sync.aligned.m8n8.x4.shared.b16 {%0,%1,%2,%3}, [%4];" \
        : "=r"((r)[0]), "=r"((r)[1]), "=r"((r)[2]), "=r"((r)[3]) : "r"(addr))

__device__ __forceinline__ uint32_t smem_u32(const void* p) {
    uint32_t a;
    asm("{ .reg .u64 t; cvta.to.shared.u64 t, %1; cvt.u32.u64 %0, t; }" : "=r"(a) : "l"(p));
    return a;
}

// ================= bf16 2-split mma.sync GEMM (R15, proven) ==================
#define BG_LD   264
#define BG_AHI  0
#define BG_ALO  (128 * BG_LD)
#define BG_BHI  (2 * 128 * BG_LD)
#define BG_BLO  (2 * 128 * BG_LD + 64 * BG_LD)
#define BG_SMEM ((2 * 128 * BG_LD + 2 * 64 * BG_LD) * 2)

__global__ void __launch_bounds__(512, 1) bgemm(
    const float* __restrict__ A, const float* __restrict__ W,
    const float* __restrict__ b1, const float* __restrict__ b2,
    float* __restrict__ C, int Ntot)
{
    extern __shared__ __align__(16) unsigned short bsm[];

    int tid = threadIdx.x;
    int wid = tid >> 5, lane = tid & 31;
    int g = lane >> 2, t = lane & 3;
    int warpM = wid >> 1, warpN = wid & 1;

    int nN = Ntot >> 6;
    int NT = nN << 5;
    int per = (NT + gridDim.x - 1) / gridDim.x;
    int tau0 = blockIdx.x * per;
    int tau1 = tau0 + per; if (tau1 > NT) tau1 = NT;
    int mPrev = -1;

    uint32_t sbase = smem_u32(bsm);
    int aRow = warpM * 16;
    int bRow = warpN * 32;
    int aOff = (aRow + (lane & 15)) * BG_LD + ((lane >> 4) << 3);
    int bRowLane = bRow + (lane >> 4) * 8 + (lane & 7);
    int bColBlk = ((lane >> 3) & 1) << 3;
    int bOff01 = bRowLane * BG_LD + bColBlk;
    int bOff23 = (bRowLane + 16) * BG_LD + bColBlk;

    for (int tau = tau0; tau < tau1; tau++) {
        int mT = tau / nN, nT = tau - mT * nN;
        int m0 = mT << 7, n0 = nT << 6;

        __syncthreads();
        if (mT != mPrev) {
            const float* Ap = A + (size_t)m0 * 256;
#pragma unroll
            for (int v = 0; v < 16; v++) {
                int id = tid + 512 * v;
                int r = id >> 6, c4 = (id & 63) * 4;
                float4 a = __ldg((const float4*)(Ap + (size_t)r * 256 + c4));
                int hidx = r * BG_LD + c4;
                split_store4(bsm + BG_AHI + hidx, bsm + BG_ALO + hidx, a);
            }
            mPrev = mT;
        }
        {
            const float* Wp = W + (size_t)n0 * 256;
#pragma unroll
            for (int v = 0; v < 8; v++) {
                int id = tid + 512 * v;
                int r = id >> 6, c4 = (id & 63) * 4;
                float4 a = __ldg((const float4*)(Wp + (size_t)r * 256 + c4));
                int hidx = r * BG_LD + c4;
                split_store4(bsm + BG_BHI + hidx, bsm + BG_BLO + hidx, a);
            }
        }
        __syncthreads();

        float acc[4][4];
#pragma unroll
        for (int j = 0; j < 4; j++)
#pragma unroll
            for (int k = 0; k < 4; k++) acc[j][k] = 0.f;

#pragma unroll 2
        for (int kk = 0; kk < 256; kk += 16) {
            uint32_t ah[4], al[4];
            LDSM_X4(ah, sbase + (uint32_t)(BG_AHI + aOff + kk) * 2);
            LDSM_X4(al, sbase + (uint32_t)(BG_ALO + aOff + kk) * 2);
            uint32_t bh01[4], bh23[4], bl01[4], bl23[4];
            LDSM_X4(bh01, sbase + (uint32_t)(BG_BHI + bOff01 + kk) * 2);
            LDSM_X4(bh23, sbase + (uint32_t)(BG_BHI + bOff23 + kk) * 2);
            LDSM_X4(bl01, sbase + (uint32_t)(BG_BLO + bOff01 + kk) * 2);
            LDSM_X4(bl23, sbase + (uint32_t)(BG_BLO + bOff23 + kk) * 2);

            MMA_BF16(acc[0], ah, &bh01[0]);
            MMA_BF16(acc[1], ah, &bh01[2]);
            MMA_BF16(acc[2], ah, &bh23[0]);
            MMA_BF16(acc[3], ah, &bh23[2]);
            MMA_BF16(acc[0], ah, &bl01[0]);
            MMA_BF16(acc[1], ah, &bl01[2]);
            MMA_BF16(acc[2], ah, &bl23[0]);
            MMA_BF16(acc[3], ah, &bl23[2]);
            MMA_BF16(acc[0], al, &bh01[0]);
            MMA_BF16(acc[1], al, &bh01[2]);
            MMA_BF16(acc[2], al, &bh23[0]);
            MMA_BF16(acc[3], al, &bh23[2]);
        }

        {
            int row0 = m0 + aRow + g;
#pragma unroll
            for (int ns = 0; ns < 4; ns++) {
                int col = n0 + bRow + ns * 8 + 2 * t;
                float bv0 = __ldg(b1 + col), bv1 = __ldg(b1 + col + 1);
                if (b2) { bv0 += __ldg(b2 + col); bv1 += __ldg(b2 + col + 1); }
                float2 o0, o1;
                o0.x = acc[ns][0] + bv0; o0.y = acc[ns][1] + bv1;
                o1.x = acc[ns][2] + bv0; o1.y = acc[ns][3] + bv1;
                *(float2*)(C + (size_t)row0 * Ntot + col) = o0;
                *(float2*)(C + (size_t)(row0 + 8) * Ntot + col) = o1;
            }
        }
    }
}

// ---------------- embedding --------------------------------------------------
__global__ void embed_k(const int* __restrict__ tok,
                        const float* __restrict__ emb,
                        float* __restrict__ out, int dec)
{
    int row = blockIdx.x;
    int tid = threadIdx.x;
    int t;
    if (dec) t = (row < B_SZ) ? 0 : tok[row - B_SZ];
    else     t = tok[row];
    out[row * H_SZ + tid] = emb[(size_t)t * H_SZ + tid];
}

// ---------------- clustered recurrence (HMMA, W frags in registers) -----------
// 16 clusters x 8 CTAs; cluster owns 4 batches, CTA rank owns 32 hidden cols
// (128 gate rows). Per step: G[4,128] = h[4,256] @ Wsl[128,256]^T via
// mma.sync bf16 2-split (3 terms). W fragments preloaded into registers.
// h exchanged as bf16 hi/lo planes via DSMEM; cluster barrier per step.
#define RPL_LD    264                       // halves per plane row
#define RPL_PLANE (16 * RPL_LD)             // 4224 halves per plane
#define RPL_IDX(buf, pl) (((buf) * 2 + (pl)) * RPL_PLANE)
#define R_OFF_GBUF  33792                   // 4 planes * 4224 * 2B
#define R_OFF_STG   (R_OFF_GBUF + 4 * 132 * 4)   // 35904
#define REC_SMEM_BYTES (R_OFF_STG + 512)    // 36416

__device__ __forceinline__ float sigf(float x)   { return __fdividef(1.f, 1.f + __expf(-x)); }
__device__ __forceinline__ float tanh_f(float x) { float e = __expf(2.f * x); return __fdividef(e - 1.f, e + 1.f); }

__global__ void __launch_bounds__(256, 1) recl_k(
    const float* __restrict__ Gx, const float* __restrict__ Whh,
    const float* __restrict__ hinit, int hbcast,
    const float* __restrict__ cinit, int cbcast,
    float* __restrict__ Xout, float* __restrict__ hfin, float* __restrict__ cfin)
{
    extern __shared__ __align__(16) char rs[];
    unsigned short* planes = (unsigned short*)rs;
    float* gbuf = (float*)(rs + R_OFF_GBUF);       // [4][132]
    unsigned short* stg = (unsigned short*)(rs + R_OFF_STG);  // [2][4][32]

    int tid  = threadIdx.x;
    int rank = blockIdx.x & 7;
    int grp  = blockIdx.x >> 3;
    int wid = tid >> 5, lane = tid & 31;
    int g = lane >> 2, t4 = lane & 3;

    uint32_t sb = smem_u32(rs);

    // ---- preload W fragments into registers (hi/lo, 2 n-tiles, 16 k-steps) --
    uint32_t bh[16][2][2], bl[16][2][2];
#pragma unroll
    for (int kt = 0; kt < 16; kt++) {
#pragma unroll
        for (int nt = 0; nt < 2; nt++) {
            int rl = 16 * wid + 8 * nt + g;          // local gate row
            int q = rl >> 5, c = rl & 31;
            const float* wr = Whh + (size_t)(q * 256 + 32 * rank + c) * 256
                            + kt * 16 + 2 * t4;
            float w0 = __ldg(wr),     w1 = __ldg(wr + 1);
            float w2 = __ldg(wr + 8), w3 = __ldg(wr + 9);
            unsigned short h0, h1, h2, h3, l0, l1, l2, l3;
            split_bf(w0, h0, l0); split_bf(w1, h1, l1);
            split_bf(w2, h2, l2); split_bf(w3, h3, l3);
            bh[kt][nt][0] = pack_bf2(h0, h1); bh[kt][nt][1] = pack_bf2(h2, h3);
            bl[kt][nt][0] = pack_bf2(l0, l1); bl[kt][nt][1] = pack_bf2(l2, l3);
        }
    }

    // ---- zero all plane buffers (rows 4-15 must stay zero) ----
    {
        uint32_t* pw = (uint32_t*)rs;
        for (int i = tid; i < (4 * RPL_PLANE) / 2; i += 256) pw[i] = 0;
    }
    __syncthreads();

    // ---- h0 -> buffer 0 planes (rows 0-3), local full copy ----
#pragma unroll
    for (int v = 0; v < 4; v++) {
        int e = tid + 256 * v;        // 1024 = 4b x 256 cols
        int b = e >> 8, col = e & 255;
        float h0 = hbcast ? __ldg(hinit + col)
                          : __ldg(hinit + (size_t)(4 * grp + b) * 256 + col);
        unsigned short hh, hl;
        split_bf(h0, hh, hl);
        planes[RPL_IDX(0, 0) + b * RPL_LD + col] = hh;
        planes[RPL_IDX(0, 1) + b * RPL_LD + col] = hl;
    }

    int ab = tid >> 5, acol = tid & 31;     // activation map (tid<128)
    int b_glob = 4 * grp + ab;
    int col_glob = 32 * rank + acol;
    float creg = 0.f, hlast = 0.f;
    if (tid < 128)
        creg = cbcast ? cinit[col_glob] : cinit[(size_t)b_glob * 256 + col_glob];

    uint32_t peer[8];
#pragma unroll
    for (int p = 0; p < 8; p++) {
        uint32_t pa;
        asm("mapa.shared::cluster.u32 %0, %1, %2;" : "=r"(pa) : "r"(sb), "r"(p));
        peer[p] = pa;
    }
    __syncthreads();
    // initial cluster sync: all CTAs' plane zeroing complete before any peer
    // pushes into buffer 1.
    asm volatile("barrier.cluster.arrive.aligned;" ::: "memory");
    asm volatile("barrier.cluster.wait.aligned;" ::: "memory");

    // per-lane ldmatrix row offset within a plane (halves)
    uint32_t aLane = (uint32_t)((lane & 15) * RPL_LD + ((lane >> 4) << 3));

    for (int t = 0; t < T_STEPS; t++) {
        // Gx prefetch before the wait (hides L2 latency + skew)
        float gx0 = 0.f, gx1 = 0.f, gx2 = 0.f, gx3 = 0.f;
        if (tid < 128) {
            const float* gp = Gx + (size_t)(t * 64 + b_glob) * 1024 + col_glob;
            gx0 = __ldcg(gp);       gx1 = __ldcg(gp + 256);
            gx2 = __ldcg(gp + 512); gx3 = __ldcg(gp + 768);
        }
        if (t > 0)
            asm volatile("barrier.cluster.wait.aligned;" ::: "memory");

        int bufc = t & 1, bufn = bufc ^ 1;
        uint32_t hiBase = sb + (uint32_t)(RPL_IDX(bufc, 0)) * 2;
        uint32_t loBase = sb + (uint32_t)(RPL_IDX(bufc, 1)) * 2;

        float acc0[4] = {0.f, 0.f, 0.f, 0.f};
        float acc1[4] = {0.f, 0.f, 0.f, 0.f};
#pragma unroll
        for (int kt = 0; kt < 16; kt++) {
            uint32_t ah[4], al[4];
            LDSM_X4(ah, hiBase + (aLane + kt * 16) * 2);
            LDSM_X4(al, loBase + (aLane + kt * 16) * 2);
            MMA_BF16(acc0, ah, bh[kt][0]);
            MMA_BF16(acc1, ah, bh[kt][1]);
            MMA_BF16(acc0, ah, bl[kt][0]);
            MMA_BF16(acc1, ah, bl[kt][1]);
            MMA_BF16(acc0, al, bh[kt][0]);
            MMA_BF16(acc1, al, bh[kt][1]);
        }

        // write G (lanes 0-15 hold valid batch rows g=0..3)
        if (lane < 16) {
            float* gr = gbuf + g * 132;
            *(float2*)(gr + 16 * wid + 2 * t4)     = make_float2(acc0[0], acc0[1]);
            *(float2*)(gr + 16 * wid + 8 + 2 * t4) = make_float2(acc1[0], acc1[1]);
        }
        __syncthreads();

        // activation + local bf16 staging
        if (tid < 128) {
            const float* gr = gbuf + ab * 132;
            float iv = gr[0 * 32 + acol] + gx0;
            float fv = gr[1 * 32 + acol] + gx1;
            float gv = gr[2 * 32 + acol] + gx2;
            float ov = gr[3 * 32 + acol] + gx3;
            float cn = sigf(fv) * creg + sigf(iv) * tanh_f(gv);
            float hn = sigf(ov) * tanh_f(cn);
            creg = cn; hlast = hn;
            Xout[(size_t)(t * 64 + b_glob) * 256 + col_glob] = hn;
            unsigned short hh, hl;
            split_bf(hn, hh, hl);
            stg[0 * 128 + ab * 32 + acol] = hh;
            stg[1 * 128 + ab * 32 + acol] = hl;
        }
        __syncthreads();

        // DSMEM broadcast (u32 pairs) into next buffer of all peers
        if (tid < 128) {
            int pl = tid >> 6;
            int e = tid & 63;
            int b = e >> 4, cp = e & 15;
            uint32_t val = *(const uint32_t*)(stg + pl * 128 + b * 32 + 2 * cp);
            uint32_t boff = (uint32_t)(RPL_IDX(bufn, pl) + b * RPL_LD
                                       + 32 * rank + 2 * cp) * 2;
#pragma unroll
            for (int p = 0; p < 8; p++)
                asm volatile("st.shared::cluster.u32 [%0], %1;"
                             :: "r"(peer[p] + boff), "r"(val) : "memory");
        }
        asm volatile("barrier.cluster.arrive.aligned;" ::: "memory");
    }
    asm volatile("barrier.cluster.wait.aligned;" ::: "memory");

    if (tid < 128) {
        cfin[(size_t)b_glob * 256 + col_glob] = creg;
        hfin[(size_t)b_glob * 256 + col_glob] = hlast;
    }
}

// ---------------- row argmax over V (float4) ----------------------------------
__global__ void argmax_k(const float* __restrict__ logits, float* __restrict__ outIdx)
{
    int m = blockIdx.x;
    const float4* row = (const float4*)(logits + (size_t)m * V_SZ);
    int tid = threadIdx.x;
    float bv = -__int_as_float(0x7f800000);
    int bi = 0;
    for (int n4 = tid; n4 < V_SZ / 4; n4 += 256) {
        float4 v = row[n4];
        int base = n4 * 4;
        if (v.x > bv) { bv = v.x; bi = base; }
        if (v.y > bv) { bv = v.y; bi = base + 1; }
        if (v.z > bv) { bv = v.z; bi = base + 2; }
        if (v.w > bv) { bv = v.w; bi = base + 3; }
    }
    __shared__ float sv[256];
    __shared__ int   si[256];
    sv[tid] = bv; si[tid] = bi;
    __syncthreads();
    for (int s = 128; s > 0; s >>= 1) {
        if (tid < s) {
            float ov = sv[tid + s]; int oi = si[tid + s];
            if (ov > sv[tid] || (ov == sv[tid] && oi < si[tid])) { sv[tid] = ov; si[tid] = oi; }
        }
        __syncthreads();
    }
    if (tid == 0) outIdx[m] = (float)si[0];
}

// ---------------- cluster launch helper ---------------------------------------
static void launch_recl(const float* gx, const float* whh,
                        const float* hinit, int hbcast,
                        const float* cinit, int cbcast,
                        float* xout, float* hfin, float* cfin)
{
    cudaLaunchConfig_t cfg = {};
    cfg.gridDim = {128, 1, 1};
    cfg.blockDim = {256, 1, 1};
    cfg.dynamicSmemBytes = REC_SMEM_BYTES;
    cfg.stream = 0;
    cudaLaunchAttribute at[1];
    at[0].id = cudaLaunchAttributeClusterDimension;
    at[0].val.clusterDim = {8, 1, 1};
    cfg.attrs = at;
    cfg.numAttrs = 1;
    cudaLaunchKernelEx(&cfg, recl_k, gx, whh, hinit, hbcast, cinit, cbcast,
                       xout, hfin, cfin);
}

// ---------------- launch ------------------------------------------------------
extern "C" void kernel_launch(void* const* d_in, const int* in_sizes, int n_in,
                              void* d_out, int out_size)
{
    const int* inputs  = (const int*)d_in[0];
    const int* targets = (const int*)d_in[1];
    const float* enc_emb = (const float*)d_in[2];
    const float* enc_Wih = (const float*)d_in[3];
    const float* enc_Whh = (const float*)d_in[4];
    const float* enc_bih = (const float*)d_in[5];
    const float* enc_bhh = (const float*)d_in[6];
    const float* hidden0 = (const float*)d_in[7];
    const float* cell0   = (const float*)d_in[8];
    const float* dec_emb = (const float*)d_in[9];
    const float* dec_Wih = (const float*)d_in[10];
    const float* dec_Whh = (const float*)d_in[11];
    const float* dec_bih = (const float*)d_in[12];
    const float* dec_bhh = (const float*)d_in[13];
    const float* fc_W    = (const float*)d_in[14];
    const float* fc_b    = (const float*)d_in[15];
    float* out = (float*)d_out;

    float *bufA, *bufB, *gx, *hfin, *cfin;
    cudaGetSymbolAddress((void**)&bufA, g_bufA);
    cudaGetSymbolAddress((void**)&bufB, g_bufB);
    cudaGetSymbolAddress((void**)&gx,   g_gx);
    cudaGetSymbolAddress((void**)&hfin, g_hfin);
    cudaGetSymbolAddress((void**)&cfin, g_cfin);

    cudaFuncSetAttribute(recl_k, cudaFuncAttributeMaxDynamicSharedMemorySize, REC_SMEM_BYTES);
    cudaFuncSetAttribute(bgemm,  cudaFuncAttributeMaxDynamicSharedMemorySize, BG_SMEM);

    float* cur = bufA;
    float* nxt = bufB;

    // ---- encoder ----
    embed_k<<<M_TOT, 256>>>(inputs, enc_emb, cur, 0);
    for (int l = 0; l < 3; l++) {
        bgemm<<<148, 512, BG_SMEM>>>(cur, enc_Wih + (size_t)l * G_SZ * H_SZ,
                                     enc_bih + l * G_SZ, enc_bhh + l * G_SZ,
                                     gx, G_SZ);
        launch_recl(gx, enc_Whh + (size_t)l * G_SZ * H_SZ,
                    hidden0 + l * H_SZ, 1, cell0 + l * H_SZ, 1,
                    nxt, hfin + (size_t)l * B_SZ * H_SZ,
                    cfin + (size_t)l * B_SZ * H_SZ);
        float* tmp = cur; cur = nxt; nxt = tmp;
    }

    // ---- decoder (teacher forcing, shifted targets) ----
    embed_k<<<M_TOT, 256>>>(targets, dec_emb, cur, 1);
    for (int l = 0; l < 3; l++) {
        bgemm<<<148, 512, BG_SMEM>>>(cur, dec_Wih + (size_t)l * G_SZ * H_SZ,
                                     dec_bih + l * G_SZ, dec_bhh + l * G_SZ,
                                     gx, G_SZ);
        launch_recl(gx, dec_Whh + (size_t)l * G_SZ * H_SZ,
                    hfin + (size_t)l * B_SZ * H_SZ, 0,
                    cfin + (size_t)l * B_SZ * H_SZ, 0,
                    nxt, hfin + (size_t)l * B_SZ * H_SZ,
                    cfin + (size_t)l * B_SZ * H_SZ);
        float* tmp = cur; cur = nxt; nxt = tmp;
    }

    // ---- FC projection to vocab (bf16 2-split mma.sync) ----
    bgemm<<<148, 512, BG_SMEM>>>(cur, fc_W, fc_b, (const float*)nullptr, out, V_SZ);

    // ---- predicted words ----
    long long need = (long long)M_TOT * V_SZ + M_TOT;
    if ((long long)out_size >= need)
        argmax_k<<<M_TOT, 256>>>(out, out + (size_t)M_TOT * V_SZ);
}

// round 17
// speedup vs baseline: 1.3202x; 1.0222x over previous
#include <cuda_runtime.h>
#include <cuda_bf16.h>
#include <math.h>
#include <stdint.h>

#define T_STEPS 64
#define B_SZ    64
#define H_SZ    256
#define G_SZ    1024
#define M_TOT   4096      // T*B
#define V_SZ    32000

// ---------------- scratch ----------------------------------------------------
__device__ __align__(256) float g_bufA[M_TOT * H_SZ];
__device__ __align__(256) float g_bufB[M_TOT * H_SZ];
__device__ __align__(256) float g_gx[M_TOT * G_SZ];
__device__ __align__(256) float g_hfin[3 * B_SZ * H_SZ];
__device__ __align__(256) float g_cfin[3 * B_SZ * H_SZ];
__device__ __align__(256) unsigned long long g_amax[M_TOT];

// ================= bf16 2-split helpers ======================================
__device__ __forceinline__ uint32_t pack_bf2(unsigned short lo, unsigned short hi) {
    return ((uint32_t)hi << 16) | (uint32_t)lo;
}
__device__ __forceinline__ void split_bf(float a, unsigned short& h, unsigned short& l) {
    __nv_bfloat16 hb = __float2bfloat16_rn(a);
    float hf = __bfloat162float(hb);
    __nv_bfloat16 lb = __float2bfloat16_rn(a - hf);
    h = __bfloat16_as_ushort(hb);
    l = __bfloat16_as_ushort(lb);
}
__device__ __forceinline__ void split_store4(unsigned short* dhi, unsigned short* dlo, float4 a) {
    unsigned short h0, h1, h2, h3, l0, l1, l2, l3;
    split_bf(a.x, h0, l0); split_bf(a.y, h1, l1);
    split_bf(a.z, h2, l2); split_bf(a.w, h3, l3);
    uint2 hv; hv.x = pack_bf2(h0, h1); hv.y = pack_bf2(h2, h3);
    uint2 lv; lv.x = pack_bf2(l0, l1); lv.y = pack_bf2(l2, l3);
    *(uint2*)dhi = hv;
    *(uint2*)dlo = lv;
}

#define MMA_BF16(c, a, b) \
    asm volatile("mma.sync.aligned.m16n8k16.row.col.f32.bf16.bf16.f32 " \
        "{%0,%1,%2,%3}, {%4,%5,%6,%7}, {%8,%9}, {%0,%1,%2,%3};" \
        : "+f"((c)[0]), "+f"((c)[1]), "+f"((c)[2]), "+f"((c)[3]) \
        : "r"((a)[0]), "r"((a)[1]), "r"((a)[2]), "r"((a)[3]), \
          "r"((b)[0]), "r"((b)[1]))

#define LDSM_X4(r, addr) \
    asm volatile("ldmatrix.sync.aligned.m8n8.x4.shared.b16 {%0,%1,%2,%3}, [%4];" \
        : "=r"((r)[0]), "=r"((r)[1]), "=r"((r)[2]), "=r"((r)[3]) : "r"(addr))

__device__ __forceinline__ uint32_t smem_u32(const void* p) {
    uint32_t a;
    asm("{ .reg .u64 t; cvta.to.shared.u64 t, %1; cvt.u32.u64 %0, t; }" : "=r"(a) : "l"(p));
    return a;
}

// argmax key: monotone float map, tie-break = lowest column
__device__ __forceinline__ unsigned long long amax_key(float v, int col) {
    uint32_t u = __float_as_uint(v);
    u = (u & 0x80000000u) ? ~u : (u | 0x80000000u);
    return ((unsigned long long)u << 32) | (unsigned long long)(0xFFFFFFFFu - (uint32_t)col);
}

// ================= bf16 2-split mma.sync GEMM (R15 core + fused argmax) ======
#define BG_LD   264
#define BG_AHI  0
#define BG_ALO  (128 * BG_LD)
#define BG_BHI  (2 * 128 * BG_LD)
#define BG_BLO  (2 * 128 * BG_LD + 64 * BG_LD)
#define BG_SMEM ((2 * 128 * BG_LD + 2 * 64 * BG_LD) * 2)

__global__ void __launch_bounds__(512, 1) bgemm(
    const float* __restrict__ A, const float* __restrict__ W,
    const float* __restrict__ b1, const float* __restrict__ b2,
    float* __restrict__ C, int Ntot, unsigned long long* __restrict__ amax)
{
    extern __shared__ __align__(16) unsigned short bsm[];

    int tid = threadIdx.x;
    int wid = tid >> 5, lane = tid & 31;
    int g = lane >> 2, t = lane & 3;
    int warpM = wid >> 1, warpN = wid & 1;

    int nN = Ntot >> 6;
    int NT = nN << 5;
    int per = (NT + gridDim.x - 1) / gridDim.x;
    int tau0 = blockIdx.x * per;
    int tau1 = tau0 + per; if (tau1 > NT) tau1 = NT;
    int mPrev = -1;

    uint32_t sbase = smem_u32(bsm);
    int aRow = warpM * 16;
    int bRow = warpN * 32;
    int aOff = (aRow + (lane & 15)) * BG_LD + ((lane >> 4) << 3);
    int bRowLane = bRow + (lane >> 4) * 8 + (lane & 7);
    int bColBlk = ((lane >> 3) & 1) << 3;
    int bOff01 = bRowLane * BG_LD + bColBlk;
    int bOff23 = (bRowLane + 16) * BG_LD + bColBlk;

    for (int tau = tau0; tau < tau1; tau++) {
        int mT = tau / nN, nT = tau - mT * nN;
        int m0 = mT << 7, n0 = nT << 6;

        __syncthreads();
        if (mT != mPrev) {
            const float* Ap = A + (size_t)m0 * 256;
#pragma unroll
            for (int v = 0; v < 16; v++) {
                int id = tid + 512 * v;
                int r = id >> 6, c4 = (id & 63) * 4;
                float4 a = __ldg((const float4*)(Ap + (size_t)r * 256 + c4));
                int hidx = r * BG_LD + c4;
                split_store4(bsm + BG_AHI + hidx, bsm + BG_ALO + hidx, a);
            }
            mPrev = mT;
        }
        {
            const float* Wp = W + (size_t)n0 * 256;
#pragma unroll
            for (int v = 0; v < 8; v++) {
                int id = tid + 512 * v;
                int r = id >> 6, c4 = (id & 63) * 4;
                float4 a = __ldg((const float4*)(Wp + (size_t)r * 256 + c4));
                int hidx = r * BG_LD + c4;
                split_store4(bsm + BG_BHI + hidx, bsm + BG_BLO + hidx, a);
            }
        }
        __syncthreads();

        float acc[4][4];
#pragma unroll
        for (int j = 0; j < 4; j++)
#pragma unroll
            for (int k = 0; k < 4; k++) acc[j][k] = 0.f;

#pragma unroll 2
        for (int kk = 0; kk < 256; kk += 16) {
            uint32_t ah[4], al[4];
            LDSM_X4(ah, sbase + (uint32_t)(BG_AHI + aOff + kk) * 2);
            LDSM_X4(al, sbase + (uint32_t)(BG_ALO + aOff + kk) * 2);
            uint32_t bh01[4], bh23[4], bl01[4], bl23[4];
            LDSM_X4(bh01, sbase + (uint32_t)(BG_BHI + bOff01 + kk) * 2);
            LDSM_X4(bh23, sbase + (uint32_t)(BG_BHI + bOff23 + kk) * 2);
            LDSM_X4(bl01, sbase + (uint32_t)(BG_BLO + bOff01 + kk) * 2);
            LDSM_X4(bl23, sbase + (uint32_t)(BG_BLO + bOff23 + kk) * 2);

            MMA_BF16(acc[0], ah, &bh01[0]);
            MMA_BF16(acc[1], ah, &bh01[2]);
            MMA_BF16(acc[2], ah, &bh23[0]);
            MMA_BF16(acc[3], ah, &bh23[2]);
            MMA_BF16(acc[0], ah, &bl01[0]);
            MMA_BF16(acc[1], ah, &bl01[2]);
            MMA_BF16(acc[2], ah, &bl23[0]);
            MMA_BF16(acc[3], ah, &bl23[2]);
            MMA_BF16(acc[0], al, &bh01[0]);
            MMA_BF16(acc[1], al, &bh01[2]);
            MMA_BF16(acc[2], al, &bh23[0]);
            MMA_BF16(acc[3], al, &bh23[2]);
        }

        {
            int row0 = m0 + aRow + g;
            unsigned long long k0 = 0ull, k1 = 0ull;
#pragma unroll
            for (int ns = 0; ns < 4; ns++) {
                int col = n0 + bRow + ns * 8 + 2 * t;
                float bv0 = __ldg(b1 + col), bv1 = __ldg(b1 + col + 1);
                if (b2) { bv0 += __ldg(b2 + col); bv1 += __ldg(b2 + col + 1); }
                float2 o0, o1;
                o0.x = acc[ns][0] + bv0; o0.y = acc[ns][1] + bv1;
                o1.x = acc[ns][2] + bv0; o1.y = acc[ns][3] + bv1;
                *(float2*)(C + (size_t)row0 * Ntot + col) = o0;
                *(float2*)(C + (size_t)(row0 + 8) * Ntot + col) = o1;
                if (amax) {
                    unsigned long long q;
                    q = amax_key(o0.x, col);     if (q > k0) k0 = q;
                    q = amax_key(o0.y, col + 1); if (q > k0) k0 = q;
                    q = amax_key(o1.x, col);     if (q > k1) k1 = q;
                    q = amax_key(o1.y, col + 1); if (q > k1) k1 = q;
                }
            }
            if (amax) {
#pragma unroll
                for (int s = 1; s < 4; s <<= 1) {
                    unsigned long long o;
                    o = __shfl_xor_sync(0xffffffffu, k0, s); if (o > k0) k0 = o;
                    o = __shfl_xor_sync(0xffffffffu, k1, s); if (o > k1) k1 = o;
                }
                if (t == 0) {
                    atomicMax(amax + row0, k0);
                    atomicMax(amax + row0 + 8, k1);
                }
            }
        }
    }
}

// ---------------- argmax init / decode ----------------------------------------
__global__ void amax_init_k(unsigned long long* a)
{
    a[blockIdx.x * 256 + threadIdx.x] = 0ull;
}
__global__ void amax_out_k(const unsigned long long* __restrict__ a,
                           float* __restrict__ o)
{
    int m = blockIdx.x * 256 + threadIdx.x;
    o[m] = (float)(0xFFFFFFFFu - (uint32_t)(a[m] & 0xFFFFFFFFull));
}

// ---------------- embedding --------------------------------------------------
__global__ void embed_k(const int* __restrict__ tok,
                        const float* __restrict__ emb,
                        float* __restrict__ out, int dec)
{
    int row = blockIdx.x;
    int tid = threadIdx.x;
    int t;
    if (dec) t = (row < B_SZ) ? 0 : tok[row - B_SZ];
    else     t = tok[row];
    out[row * H_SZ + tid] = emb[(size_t)t * H_SZ + tid];
}

// ---------------- clustered recurrence (HMMA, split acc chains) ---------------
#define RPL_LD    264
#define RPL_PLANE (16 * RPL_LD)
#define RPL_IDX(buf, pl) (((buf) * 2 + (pl)) * RPL_PLANE)
#define R_OFF_GBUF  33792
#define R_OFF_STG   (R_OFF_GBUF + 4 * 132 * 4)
#define REC_SMEM_BYTES (R_OFF_STG + 512)

__device__ __forceinline__ float sigf(float x)   { return __fdividef(1.f, 1.f + __expf(-x)); }
__device__ __forceinline__ float tanh_f(float x) { float e = __expf(2.f * x); return __fdividef(e - 1.f, e + 1.f); }

__global__ void __launch_bounds__(256, 1) recl_k(
    const float* __restrict__ Gx, const float* __restrict__ Whh,
    const float* __restrict__ hinit, int hbcast,
    const float* __restrict__ cinit, int cbcast,
    float* __restrict__ Xout, float* __restrict__ hfin, float* __restrict__ cfin)
{
    extern __shared__ __align__(16) char rs[];
    unsigned short* planes = (unsigned short*)rs;
    float* gbuf = (float*)(rs + R_OFF_GBUF);
    unsigned short* stg = (unsigned short*)(rs + R_OFF_STG);

    int tid  = threadIdx.x;
    int rank = blockIdx.x & 7;
    int grp  = blockIdx.x >> 3;
    int wid = tid >> 5, lane = tid & 31;
    int g = lane >> 2, t4 = lane & 3;

    uint32_t sb = smem_u32(rs);

    // ---- preload W fragments into registers ----
    uint32_t bh[16][2][2], bl[16][2][2];
#pragma unroll
    for (int kt = 0; kt < 16; kt++) {
#pragma unroll
        for (int nt = 0; nt < 2; nt++) {
            int rl = 16 * wid + 8 * nt + g;
            int q = rl >> 5, c = rl & 31;
            const float* wr = Whh + (size_t)(q * 256 + 32 * rank + c) * 256
                            + kt * 16 + 2 * t4;
            float w0 = __ldg(wr),     w1 = __ldg(wr + 1);
            float w2 = __ldg(wr + 8), w3 = __ldg(wr + 9);
            unsigned short h0, h1, h2, h3, l0, l1, l2, l3;
            split_bf(w0, h0, l0); split_bf(w1, h1, l1);
            split_bf(w2, h2, l2); split_bf(w3, h3, l3);
            bh[kt][nt][0] = pack_bf2(h0, h1); bh[kt][nt][1] = pack_bf2(h2, h3);
            bl[kt][nt][0] = pack_bf2(l0, l1); bl[kt][nt][1] = pack_bf2(l2, l3);
        }
    }

    // ---- zero plane buffers ----
    {
        uint32_t* pw = (uint32_t*)rs;
        for (int i = tid; i < (4 * RPL_PLANE) / 2; i += 256) pw[i] = 0;
    }
    __syncthreads();

    // ---- h0 -> buffer 0 ----
#pragma unroll
    for (int v = 0; v < 4; v++) {
        int e = tid + 256 * v;
        int b = e >> 8, col = e & 255;
        float h0 = hbcast ? __ldg(hinit + col)
                          : __ldg(hinit + (size_t)(4 * grp + b) * 256 + col);
        unsigned short hh, hl;
        split_bf(h0, hh, hl);
        planes[RPL_IDX(0, 0) + b * RPL_LD + col] = hh;
        planes[RPL_IDX(0, 1) + b * RPL_LD + col] = hl;
    }

    int ab = tid >> 5, acol = tid & 31;
    int b_glob = 4 * grp + ab;
    int col_glob = 32 * rank + acol;
    float creg = 0.f, hlast = 0.f;
    if (tid < 128)
        creg = cbcast ? cinit[col_glob] : cinit[(size_t)b_glob * 256 + col_glob];

    uint32_t peer[8];
#pragma unroll
    for (int p = 0; p < 8; p++) {
        uint32_t pa;
        asm("mapa.shared::cluster.u32 %0, %1, %2;" : "=r"(pa) : "r"(sb), "r"(p));
        peer[p] = pa;
    }
    __syncthreads();
    asm volatile("barrier.cluster.arrive.aligned;" ::: "memory");
    asm volatile("barrier.cluster.wait.aligned;" ::: "memory");

    uint32_t aLane = (uint32_t)((lane & 15) * RPL_LD + ((lane >> 4) << 3));

    for (int t = 0; t < T_STEPS; t++) {
        float gx0 = 0.f, gx1 = 0.f, gx2 = 0.f, gx3 = 0.f;
        if (tid < 128) {
            const float* gp = Gx + (size_t)(t * 64 + b_glob) * 1024 + col_glob;
            gx0 = __ldcg(gp);       gx1 = __ldcg(gp + 256);
            gx2 = __ldcg(gp + 512); gx3 = __ldcg(gp + 768);
        }
        if (t > 0)
            asm volatile("barrier.cluster.wait.aligned;" ::: "memory");

        int bufc = t & 1, bufn = bufc ^ 1;
        uint32_t hiBase = sb + (uint32_t)(RPL_IDX(bufc, 0)) * 2;
        uint32_t loBase = sb + (uint32_t)(RPL_IDX(bufc, 1)) * 2;

        // split accumulator chains (even/odd kt) to halve RAW depth
        float a0e[4] = {0.f,0.f,0.f,0.f}, a1e[4] = {0.f,0.f,0.f,0.f};
        float a0o[4] = {0.f,0.f,0.f,0.f}, a1o[4] = {0.f,0.f,0.f,0.f};
#pragma unroll
        for (int kt = 0; kt < 16; kt += 2) {
            uint32_t ah[4], al[4], ah2[4], al2[4];
            LDSM_X4(ah,  hiBase + (aLane + kt * 16) * 2);
            LDSM_X4(al,  loBase + (aLane + kt * 16) * 2);
            LDSM_X4(ah2, hiBase + (aLane + (kt + 1) * 16) * 2);
            LDSM_X4(al2, loBase + (aLane + (kt + 1) * 16) * 2);
            MMA_BF16(a0e, ah, bh[kt][0]);
            MMA_BF16(a1e, ah, bh[kt][1]);
            MMA_BF16(a0o, ah2, bh[kt + 1][0]);
            MMA_BF16(a1o, ah2, bh[kt + 1][1]);
            MMA_BF16(a0e, ah, bl[kt][0]);
            MMA_BF16(a1e, ah, bl[kt][1]);
            MMA_BF16(a0o, ah2, bl[kt + 1][0]);
            MMA_BF16(a1o, ah2, bl[kt + 1][1]);
            MMA_BF16(a0e, al, bh[kt][0]);
            MMA_BF16(a1e, al, bh[kt][1]);
            MMA_BF16(a0o, al2, bh[kt + 1][0]);
            MMA_BF16(a1o, al2, bh[kt + 1][1]);
        }
        float acc0[2], acc1[2];
        acc0[0] = a0e[0] + a0o[0]; acc0[1] = a0e[1] + a0o[1];
        acc1[0] = a1e[0] + a1o[0]; acc1[1] = a1e[1] + a1o[1];

        if (lane < 16) {
            float* gr = gbuf + g * 132;
            *(float2*)(gr + 16 * wid + 2 * t4)     = make_float2(acc0[0], acc0[1]);
            *(float2*)(gr + 16 * wid + 8 + 2 * t4) = make_float2(acc1[0], acc1[1]);
        }
        __syncthreads();

        if (tid < 128) {
            const float* gr = gbuf + ab * 132;
            float iv = gr[0 * 32 + acol] + gx0;
            float fv = gr[1 * 32 + acol] + gx1;
            float gv = gr[2 * 32 + acol] + gx2;
            float ov = gr[3 * 32 + acol] + gx3;
            float cn = sigf(fv) * creg + sigf(iv) * tanh_f(gv);
            float hn = sigf(ov) * tanh_f(cn);
            creg = cn; hlast = hn;
            Xout[(size_t)(t * 64 + b_glob) * 256 + col_glob] = hn;
            unsigned short hh, hl;
            split_bf(hn, hh, hl);
            stg[0 * 128 + ab * 32 + acol] = hh;
            stg[1 * 128 + ab * 32 + acol] = hl;
        }
        __syncthreads();

        if (tid < 128) {
            int pl = tid >> 6;
            int e = tid & 63;
            int b = e >> 4, cp = e & 15;
            uint32_t val = *(const uint32_t*)(stg + pl * 128 + b * 32 + 2 * cp);
            uint32_t boff = (uint32_t)(RPL_IDX(bufn, pl) + b * RPL_LD
                                       + 32 * rank + 2 * cp) * 2;
#pragma unroll
            for (int p = 0; p < 8; p++)
                asm volatile("st.shared::cluster.u32 [%0], %1;"
                             :: "r"(peer[p] + boff), "r"(val) : "memory");
        }
        asm volatile("barrier.cluster.arrive.aligned;" ::: "memory");
    }
    asm volatile("barrier.cluster.wait.aligned;" ::: "memory");

    if (tid < 128) {
        cfin[(size_t)b_glob * 256 + col_glob] = creg;
        hfin[(size_t)b_glob * 256 + col_glob] = hlast;
    }
}

// ---------------- cluster launch helper ---------------------------------------
static void launch_recl(const float* gx, const float* whh,
                        const float* hinit, int hbcast,
                        const float* cinit, int cbcast,
                        float* xout, float* hfin, float* cfin)
{
    cudaLaunchConfig_t cfg = {};
    cfg.gridDim = {128, 1, 1};
    cfg.blockDim = {256, 1, 1};
    cfg.dynamicSmemBytes = REC_SMEM_BYTES;
    cfg.stream = 0;
    cudaLaunchAttribute at[1];
    at[0].id = cudaLaunchAttributeClusterDimension;
    at[0].val.clusterDim = {8, 1, 1};
    cfg.attrs = at;
    cfg.numAttrs = 1;
    cudaLaunchKernelEx(&cfg, recl_k, gx, whh, hinit, hbcast, cinit, cbcast,
                       xout, hfin, cfin);
}

// ---------------- launch ------------------------------------------------------
extern "C" void kernel_launch(void* const* d_in, const int* in_sizes, int n_in,
                              void* d_out, int out_size)
{
    const int* inputs  = (const int*)d_in[0];
    const int* targets = (const int*)d_in[1];
    const float* enc_emb = (const float*)d_in[2];
    const float* enc_Wih = (const float*)d_in[3];
    const float* enc_Whh = (const float*)d_in[4];
    const float* enc_bih = (const float*)d_in[5];
    const float* enc_bhh = (const float*)d_in[6];
    const float* hidden0 = (const float*)d_in[7];
    const float* cell0   = (const float*)d_in[8];
    const float* dec_emb = (const float*)d_in[9];
    const float* dec_Wih = (const float*)d_in[10];
    const float* dec_Whh = (const float*)d_in[11];
    const float* dec_bih = (const float*)d_in[12];
    const float* dec_bhh = (const float*)d_in[13];
    const float* fc_W    = (const float*)d_in[14];
    const float* fc_b    = (const float*)d_in[15];
    float* out = (float*)d_out;

    float *bufA, *bufB, *gx, *hfin, *cfin;
    unsigned long long* amax;
    cudaGetSymbolAddress((void**)&bufA, g_bufA);
    cudaGetSymbolAddress((void**)&bufB, g_bufB);
    cudaGetSymbolAddress((void**)&gx,   g_gx);
    cudaGetSymbolAddress((void**)&hfin, g_hfin);
    cudaGetSymbolAddress((void**)&cfin, g_cfin);
    cudaGetSymbolAddress((void**)&amax, g_amax);

    cudaFuncSetAttribute(recl_k, cudaFuncAttributeMaxDynamicSharedMemorySize, REC_SMEM_BYTES);
    cudaFuncSetAttribute(bgemm,  cudaFuncAttributeMaxDynamicSharedMemorySize, BG_SMEM);

    float* cur = bufA;
    float* nxt = bufB;

    // ---- encoder ----
    embed_k<<<M_TOT, 256>>>(inputs, enc_emb, cur, 0);
    for (int l = 0; l < 3; l++) {
        bgemm<<<148, 512, BG_SMEM>>>(cur, enc_Wih + (size_t)l * G_SZ * H_SZ,
                                     enc_bih + l * G_SZ, enc_bhh + l * G_SZ,
                                     gx, G_SZ, (unsigned long long*)nullptr);
        launch_recl(gx, enc_Whh + (size_t)l * G_SZ * H_SZ,
                    hidden0 + l * H_SZ, 1, cell0 + l * H_SZ, 1,
                    nxt, hfin + (size_t)l * B_SZ * H_SZ,
                    cfin + (size_t)l * B_SZ * H_SZ);
        float* tmp = cur; cur = nxt; nxt = tmp;
    }

    // ---- decoder (teacher forcing, shifted targets) ----
    embed_k<<<M_TOT, 256>>>(targets, dec_emb, cur, 1);
    for (int l = 0; l < 3; l++) {
        bgemm<<<148, 512, BG_SMEM>>>(cur, dec_Wih + (size_t)l * G_SZ * H_SZ,
                                     dec_bih + l * G_SZ, dec_bhh + l * G_SZ,
                                     gx, G_SZ, (unsigned long long*)nullptr);
        launch_recl(gx, dec_Whh + (size_t)l * G_SZ * H_SZ,
                    hfin + (size_t)l * B_SZ * H_SZ, 0,
                    cfin + (size_t)l * B_SZ * H_SZ, 0,
                    nxt, hfin + (size_t)l * B_SZ * H_SZ,
                    cfin + (size_t)l * B_SZ * H_SZ);
        float* tmp = cur; cur = nxt; nxt = tmp;
    }

    // ---- FC projection to vocab with fused argmax ----
    amax_init_k<<<M_TOT / 256, 256>>>(amax);
    bgemm<<<148, 512, BG_SMEM>>>(cur, fc_W, fc_b, (const float*)nullptr,
                                 out, V_SZ, amax);

    // ---- predicted words (decode fused result) ----
    long long need = (long long)M_TOT * V_SZ + M_TOT;
    if ((long long)out_size >= need)
        amax_out_k<<<M_TOT / 256, 256>>>(amax, out + (size_t)M_TOT * V_SZ);
}